// round 3
// baseline (speedup 1.0000x reference)
#include <cuda_runtime.h>

#define EPSV 1e-5f

// scratch (no cudaMalloc allowed)
__device__ float g_x1p[16 * 16 * 256 * 256];   // stage1 output, pooled  [N,16,256,256]
__device__ float g_mask2[16 * 256 * 256];      // pooled mask            [N,256,256]
__device__ float g_x2p[16 * 8 * 128 * 128];    // stage2 output, pooled  [N,8,128,128]
__device__ float g_fcpart[16 * 8 * 10];        // FC partial sums

typedef unsigned long long ull;

__device__ __forceinline__ void fma2(ull& d, ull a, ull b) {
    asm("fma.rn.f32x2 %0, %1, %2, %0;" : "+l"(d) : "l"(a), "l"(b));
}
__device__ __forceinline__ ull pack2(float lo, float hi) {
    ull r; asm("mov.b64 %0, {%1, %2};" : "=l"(r) : "f"(lo), "f"(hi)); return r;
}
__device__ __forceinline__ ull dup2(float v) { return pack2(v, v); }
__device__ __forceinline__ float2 unpack2(ull u) {
    float2 f; asm("mov.b64 {%0, %1}, %2;" : "=f"(f.x), "=f"(f.y) : "l"(u)); return f;
}

// padded row stride (floats) for activation tiles: kills LDS bank conflicts
#define RS 20
#define CS 320   // 16 rows * RS

// ---------------------------------------------------------------------------
// Stage 1: x[16,3,512,512] -> g_x1p[16,16,256,256], mask -> g_mask2
// SMEM plan (floats):
//   s_a  [0      .. 10240)  : 32ch x CS  (d1 out, padded; later d3-out flat 16x256)
//   s_b  [10240  .. 18432)  : 32ch x 256 (d2 out, compact; s_xc aliases: 16ch x CS)
//   w2d2 [18432  .. 27648)  : 9216 (paired d2 weights)
//   w1s  [27648  .. 28160)  : 512
//   w3s  [28160  .. 28672)  : 512
// ---------------------------------------------------------------------------
__global__ void __launch_bounds__(256, 2) stage1_kernel(
    const float* __restrict__ x, const float* __restrict__ mask,
    const float* __restrict__ cw, const float* __restrict__ cb, const float* __restrict__ bn0,
    const float* __restrict__ d1w, const float* __restrict__ d1b, const float* __restrict__ bn1,
    const float* __restrict__ d2w, const float* __restrict__ d2b, const float* __restrict__ bn2,
    const float* __restrict__ d3w, const float* __restrict__ d3b, const float* __restrict__ bn3)
{
    extern __shared__ float sm[];
    float*  s_a   = sm;                  // padded [32][CS]
    float*  s_f   = sm;                  // d3 out flat [16][256] (reuses s_a)
    float*  s_b   = sm + 10240;          // compact [32][256]
    float*  s_xc  = s_b;                 // padded [16][CS] (alias, <= 8192 fl)
    float2* w2d2  = (float2*)(sm + 18432);
    float*  w2d2f = (float*)w2d2;
    float*  w1s   = sm + 27648;
    float*  w3s   = sm + 28160;

    __shared__ float s_red[256];
    __shared__ float s_wsum[8];
    __shared__ float s_sc0[16], s_sh0[16];
    __shared__ float s_sc1[32], s_sh1[32];
    __shared__ float s_sc2[32], s_sh2[32];
    __shared__ float s_sc3[16], s_sh3[16];
    __shared__ int s_active;

    const int bid = blockIdx.x;
    const int n   = bid >> 10;
    const int by  = (bid >> 5) & 31;
    const int bx  = bid & 31;
    const int tid = threadIdx.x;
    const int py  = tid >> 4, px_ = tid & 15;
    const int gy  = by * 16 + py, gx = bx * 16 + px_;

    // BN affine precompute
    if (tid < 16) {
        float g = bn0[tid], b = bn0[16 + tid], m = bn0[32 + tid], v = bn0[48 + tid];
        float s = g * rsqrtf(v + EPSV); s_sc0[tid] = s; s_sh0[tid] = b - s * m;
    } else if (tid < 48) {
        int c = tid - 16;
        float g = bn1[c], b = bn1[32 + c], m = bn1[64 + c], v = bn1[96 + c];
        float s = g * rsqrtf(v + EPSV); s_sc1[c] = s; s_sh1[c] = b - s * m;
    } else if (tid < 80) {
        int c = tid - 48;
        float g = bn2[c], b = bn2[32 + c], m = bn2[64 + c], v = bn2[96 + c];
        float s = g * rsqrtf(v + EPSV); s_sc2[c] = s; s_sh2[c] = b - s * m;
    } else if (tid < 96) {
        int c = tid - 80;
        float g = bn3[c], b = bn3[16 + c], m = bn3[32 + c], v = bn3[48 + c];
        float s = g * rsqrtf(v + EPSV); s_sc3[c] = s; s_sh3[c] = b - s * m;
    }

    // mask tile + activity
    float mval = mask[(n * 512 + gy) * 512 + gx];
    s_red[tid] = mval;
    float msum = mval;
#pragma unroll
    for (int o = 16; o; o >>= 1) msum += __shfl_xor_sync(0xffffffffu, msum, o);
    if ((tid & 31) == 0) s_wsum[tid >> 5] = msum;
    __syncthreads();

    if (tid < 64) {
        int qy = tid >> 3, qx = tid & 7;
        int p0 = (qy * 2) * 16 + qx * 2;
        float m0 = fmaxf(fmaxf(s_red[p0], s_red[p0 + 1]),
                         fmaxf(s_red[p0 + 16], s_red[p0 + 17]));
        g_mask2[(n * 256 + by * 8 + qy) * 256 + (bx * 8 + qx)] = m0;
    }
    if (tid == 0) {
        float t = 0.f;
#pragma unroll
        for (int i = 0; i < 8; i++) t += s_wsum[i];
        s_active = (t > 128.0f) ? 1 : 0;
    }
    __syncthreads();    // s_active visible

    const int act = s_active;

    // weight staging first (LDG latency overlaps channel path below)
    if (act) {
        for (int i = tid; i < 9216; i += 256) {
            int c2 = i / 288, rem = i - c2 * 288;
            int c1 = rem / 9, t = rem - c1 * 9;
            w2d2f[((c1 * 9 + t) * 16 + (c2 >> 1)) * 2 + (c2 & 1)] = d2w[i];
        }
        for (int i = tid; i < 512; i += 256) w1s[i] = d1w[i];
        for (int i = tid; i < 512; i += 256) w3s[i] = d3w[i];
    }

    // channel path: 1x1 conv 3->16 + bias, relu, bn  -> s_xc (padded)
    {
        const int ibase = ((n * 3) * 512 + gy) * 512 + gx;
        float xv0 = x[ibase];
        float xv1 = x[ibase + 512 * 512];
        float xv2 = x[ibase + 2 * 512 * 512];
        const int po = py * RS + px_;
#pragma unroll
        for (int c = 0; c < 16; c++) {
            float t = __ldg(&cw[c * 3 + 0]) * xv0 + __ldg(&cw[c * 3 + 1]) * xv1 +
                      __ldg(&cw[c * 3 + 2]) * xv2 + __ldg(&cb[c]);
            t = fmaxf(t, 0.0f);
            s_xc[c * CS + po] = fmaf(s_sc0[c], t, s_sh0[c]);
        }
    }
    __syncthreads();

    // thread maps
    const int lane  = tid & 31;
    const int prow  = lane >> 1;          // 0..15
    const int pcol  = (lane & 1) * 8;     // 0 or 8
    const int wg    = tid >> 5;           // warp id 0..7

    if (act) {
        // ---- d1: 1x1, 16 -> 32 ----  (8px x 4c2 per thread; pixel-pair accs)
        {
            const int c2base = wg * 4;
            ull acc[4][4];    // [c2][pxpair]
#pragma unroll
            for (int c2 = 0; c2 < 4; c2++) {
                ull bv = dup2(__ldg(&d1b[c2base + c2]));
                acc[c2][0] = bv; acc[c2][1] = bv; acc[c2][2] = bv; acc[c2][3] = bv;
            }
            const int po = prow * RS + pcol;
#pragma unroll
            for (int c1 = 0; c1 < 16; c1++) {
                const float* p = s_xc + c1 * CS + po;
                float4 a = *(const float4*)p;
                float4 b = *(const float4*)(p + 4);
                ull va0 = pack2(a.x, a.y), va1 = pack2(a.z, a.w);
                ull vb0 = pack2(b.x, b.y), vb1 = pack2(b.z, b.w);
#pragma unroll
                for (int c2 = 0; c2 < 4; c2++) {
                    ull w = dup2(w1s[(c2base + c2) * 16 + c1]);
                    fma2(acc[c2][0], w, va0);
                    fma2(acc[c2][1], w, va1);
                    fma2(acc[c2][2], w, vb0);
                    fma2(acc[c2][3], w, vb1);
                }
            }
#pragma unroll
            for (int c2 = 0; c2 < 4; c2++) {
                int c = c2base + c2;
                float sc = s_sc1[c], sh = s_sh1[c];
                float4 o0, o1;
                float2 f0 = unpack2(acc[c2][0]), f1 = unpack2(acc[c2][1]);
                float2 f2 = unpack2(acc[c2][2]), f3 = unpack2(acc[c2][3]);
                o0.x = fmaf(sc, fmaxf(f0.x, 0.f), sh); o0.y = fmaf(sc, fmaxf(f0.y, 0.f), sh);
                o0.z = fmaf(sc, fmaxf(f1.x, 0.f), sh); o0.w = fmaf(sc, fmaxf(f1.y, 0.f), sh);
                o1.x = fmaf(sc, fmaxf(f2.x, 0.f), sh); o1.y = fmaf(sc, fmaxf(f2.y, 0.f), sh);
                o1.z = fmaf(sc, fmaxf(f3.x, 0.f), sh); o1.w = fmaf(sc, fmaxf(f3.y, 0.f), sh);
                *(float4*)(s_a + c * CS + po)     = o0;
                *(float4*)(s_a + c * CS + po + 4) = o1;
            }
        }
        __syncthreads();

        // ---- d2: 3x3 (block-padded), 32 -> 32 ----  (8px x 4c2; channel-pair accs)
        {
            const int pairb = wg * 2;            // pairs (c2 = 2*pairb .. 2*pairb+3)
            ull acc[2][8];
#pragma unroll
            for (int p = 0; p < 2; p++) {
                int c2 = 2 * (pairb + p);
                ull bv = pack2(__ldg(&d2b[c2]), __ldg(&d2b[c2 + 1]));
#pragma unroll
                for (int k = 0; k < 8; k++) acc[p][k] = bv;
            }
            const float* sap = s_a + pcol;
#pragma unroll 4
            for (int c1 = 0; c1 < 32; c1++) {
                const float* cbase = sap + c1 * CS;
#pragma unroll
                for (int r = 0; r < 3; r++) {
                    int yy = prow - 1 + r;
                    float u0, u9; float4 m1, m2;
                    if ((unsigned)yy < 16u) {
                        const float* rp = cbase + yy * RS;
                        m1 = *(const float4*)rp;
                        m2 = *(const float4*)(rp + 4);
                        u0 = pcol ? rp[-1] : 0.f;
                        u9 = pcol ? 0.f : rp[8];
                    } else {
                        m1 = make_float4(0.f, 0.f, 0.f, 0.f);
                        m2 = m1; u0 = 0.f; u9 = 0.f;
                    }
                    ull vd[10] = {dup2(u0), dup2(m1.x), dup2(m1.y), dup2(m1.z), dup2(m1.w),
                                  dup2(m2.x), dup2(m2.y), dup2(m2.z), dup2(m2.w), dup2(u9)};
                    const float2* wrow = w2d2 + (c1 * 9 + r * 3) * 16 + pairb;
#pragma unroll
                    for (int dx = 0; dx < 3; dx++) {
                        ulonglong2 w = *(const ulonglong2*)(wrow + dx * 16);
#pragma unroll
                        for (int k = 0; k < 8; k++) {
                            fma2(acc[0][k], w.x, vd[dx + k]);
                            fma2(acc[1][k], w.y, vd[dx + k]);
                        }
                    }
                }
            }
            // epilogue -> s_b compact (overwrites s_xc alias; d1 reads done)
            const int poc = prow * 16 + pcol;
#pragma unroll
            for (int p = 0; p < 2; p++) {
                int c2 = 2 * (pairb + p);
                float sa = s_sc2[c2], ha = s_sh2[c2];
                float sb2 = s_sc2[c2 + 1], hb = s_sh2[c2 + 1];
                float4 oa0, oa1, ob0, ob1;
                float2 f;
                f = unpack2(acc[p][0]); oa0.x = fmaf(sa, fmaxf(f.x,0.f), ha); ob0.x = fmaf(sb2, fmaxf(f.y,0.f), hb);
                f = unpack2(acc[p][1]); oa0.y = fmaf(sa, fmaxf(f.x,0.f), ha); ob0.y = fmaf(sb2, fmaxf(f.y,0.f), hb);
                f = unpack2(acc[p][2]); oa0.z = fmaf(sa, fmaxf(f.x,0.f), ha); ob0.z = fmaf(sb2, fmaxf(f.y,0.f), hb);
                f = unpack2(acc[p][3]); oa0.w = fmaf(sa, fmaxf(f.x,0.f), ha); ob0.w = fmaf(sb2, fmaxf(f.y,0.f), hb);
                f = unpack2(acc[p][4]); oa1.x = fmaf(sa, fmaxf(f.x,0.f), ha); ob1.x = fmaf(sb2, fmaxf(f.y,0.f), hb);
                f = unpack2(acc[p][5]); oa1.y = fmaf(sa, fmaxf(f.x,0.f), ha); ob1.y = fmaf(sb2, fmaxf(f.y,0.f), hb);
                f = unpack2(acc[p][6]); oa1.z = fmaf(sa, fmaxf(f.x,0.f), ha); ob1.z = fmaf(sb2, fmaxf(f.y,0.f), hb);
                f = unpack2(acc[p][7]); oa1.w = fmaf(sa, fmaxf(f.x,0.f), ha); ob1.w = fmaf(sb2, fmaxf(f.y,0.f), hb);
                *(float4*)(s_b + c2 * 256 + poc)           = oa0;
                *(float4*)(s_b + c2 * 256 + poc + 4)       = oa1;
                *(float4*)(s_b + (c2 + 1) * 256 + poc)     = ob0;
                *(float4*)(s_b + (c2 + 1) * 256 + poc + 4) = ob1;
            }
        }
        __syncthreads();

        // ---- d3: 1x1, 32 -> 16 ----  (coalesced quad map; pixel-pair accs)
        {
            const int q      = tid & 63;         // pixel quad
            const int c2base = (tid >> 6) * 4;   // 4 of 16 channels
            ull acc[4][2];
#pragma unroll
            for (int c2 = 0; c2 < 4; c2++) {
                ull bv = dup2(__ldg(&d3b[c2base + c2]));
                acc[c2][0] = bv; acc[c2][1] = bv;
            }
#pragma unroll 4
            for (int c1 = 0; c1 < 32; c1++) {
                float4 v = *(const float4*)(s_b + c1 * 256 + q * 4);
                ull v0 = pack2(v.x, v.y), v1 = pack2(v.z, v.w);
#pragma unroll
                for (int c2 = 0; c2 < 4; c2++) {
                    ull w = dup2(w3s[(c2base + c2) * 32 + c1]);
                    fma2(acc[c2][0], w, v0);
                    fma2(acc[c2][1], w, v1);
                }
            }
#pragma unroll
            for (int c2 = 0; c2 < 4; c2++) {
                int c = c2base + c2;
                float sc = s_sc3[c], sh = s_sh3[c];
                float2 f0 = unpack2(acc[c2][0]), f1 = unpack2(acc[c2][1]);
                float4 o;
                o.x = fmaf(sc, fmaxf(f0.x, 0.f), sh);
                o.y = fmaf(sc, fmaxf(f0.y, 0.f), sh);
                o.z = fmaf(sc, fmaxf(f1.x, 0.f), sh);
                o.w = fmaf(sc, fmaxf(f1.y, 0.f), sh);
                *(float4*)(s_f + c * 256 + q * 4) = o;
            }
        }
        __syncthreads();
    }

    // fused 2x2 maxpool -> g_x1p
    const float* srcp = act ? s_f : s_xc;
    const int chs = act ? 256 : CS;
    const int rs  = act ? 16 : RS;
#pragma unroll
    for (int k = 0; k < 4; k++) {
        int o = tid + k * 256;
        int c = o >> 6;
        int q = o & 63;
        int qy = q >> 3, qx = q & 7;
        const float* sp = &srcp[c * chs + (qy * 2) * rs + qx * 2];
        float mo = fmaxf(fmaxf(sp[0], sp[1]), fmaxf(sp[rs], sp[rs + 1]));
        g_x1p[((n * 16 + c) * 256 + by * 8 + qy) * 256 + (bx * 8 + qx)] = mo;
    }
}

// ---------------------------------------------------------------------------
// Stage 2: g_x1p[16,16,256,256] -> g_x2p[16,8,128,128]
// SMEM (floats): s_a [0..5120) padded 16xCS (also d3-out flat 8x256);
//   s_b [5120..9216) compact 16x256 (s_xc alias padded 8xCS);
//   w2d2 [9216..11520); w1s [11520..11648); w3s [11648..11776)
// ---------------------------------------------------------------------------
__global__ void __launch_bounds__(256) stage2_kernel(
    const float* __restrict__ cw, const float* __restrict__ cb, const float* __restrict__ bn0,
    const float* __restrict__ d1w, const float* __restrict__ d1b, const float* __restrict__ bn1,
    const float* __restrict__ d2w, const float* __restrict__ d2b, const float* __restrict__ bn2,
    const float* __restrict__ d3w, const float* __restrict__ d3b, const float* __restrict__ bn3)
{
    extern __shared__ float sm2[];
    float*  s_a   = sm2;
    float*  s_f   = sm2;
    float*  s_b   = sm2 + 5120;
    float*  s_xc  = s_b;
    float2* w2d2  = (float2*)(sm2 + 9216);
    float*  w2d2f = (float*)w2d2;
    float*  w1s   = sm2 + 11520;
    float*  w3s   = sm2 + 11648;

    __shared__ float s_wsum[8];
    __shared__ float s_sc0[8],  s_sh0[8];
    __shared__ float s_sc1[16], s_sh1[16];
    __shared__ float s_sc2[16], s_sh2[16];
    __shared__ float s_sc3[8],  s_sh3[8];
    __shared__ int s_active;

    const int bid = blockIdx.x;
    const int n   = bid >> 8;
    const int by  = (bid >> 4) & 15;
    const int bx  = bid & 15;
    const int tid = threadIdx.x;
    const int py  = tid >> 4, px_ = tid & 15;
    const int gy  = by * 16 + py, gx = bx * 16 + px_;

    if (tid < 8) {
        float g = bn0[tid], b = bn0[8 + tid], m = bn0[16 + tid], v = bn0[24 + tid];
        float s = g * rsqrtf(v + EPSV); s_sc0[tid] = s; s_sh0[tid] = b - s * m;
    } else if (tid < 24) {
        int c = tid - 8;
        float g = bn1[c], b = bn1[16 + c], m = bn1[32 + c], v = bn1[48 + c];
        float s = g * rsqrtf(v + EPSV); s_sc1[c] = s; s_sh1[c] = b - s * m;
    } else if (tid < 40) {
        int c = tid - 24;
        float g = bn2[c], b = bn2[16 + c], m = bn2[32 + c], v = bn2[48 + c];
        float s = g * rsqrtf(v + EPSV); s_sc2[c] = s; s_sh2[c] = b - s * m;
    } else if (tid < 48) {
        int c = tid - 40;
        float g = bn3[c], b = bn3[8 + c], m = bn3[16 + c], v = bn3[24 + c];
        float s = g * rsqrtf(v + EPSV); s_sc3[c] = s; s_sh3[c] = b - s * m;
    }

    {
        float mv = g_mask2[(n * 256 + gy) * 256 + gx];
#pragma unroll
        for (int o = 16; o; o >>= 1) mv += __shfl_xor_sync(0xffffffffu, mv, o);
        if ((tid & 31) == 0) s_wsum[tid >> 5] = mv;
    }
    __syncthreads();
    if (tid == 0) {
        float t = 0.f;
#pragma unroll
        for (int i = 0; i < 8; i++) t += s_wsum[i];
        s_active = (t > 128.0f) ? 1 : 0;
    }
    __syncthreads();
    const int act = s_active;

    if (act) {
        for (int i = tid; i < 2304; i += 256) {      // d2w [16][16][9]
            int c2 = i / 144, rem = i - c2 * 144;
            int c1 = rem / 9, t = rem - c1 * 9;
            w2d2f[((c1 * 9 + t) * 8 + (c2 >> 1)) * 2 + (c2 & 1)] = d2w[i];
        }
        if (tid < 128) w1s[tid] = d1w[tid];          // [16][8]
        else if (tid < 256) w3s[tid - 128] = d3w[tid - 128];  // [8][16]
    }

    // channel path: 1x1 conv 16->8 -> s_xc (padded)
    {
        const int ibase = ((n * 16) * 256 + gy) * 256 + gx;
        float xin[16];
#pragma unroll
        for (int c = 0; c < 16; c++) xin[c] = g_x1p[ibase + c * 65536];
        const int po = py * RS + px_;
#pragma unroll
        for (int c2 = 0; c2 < 8; c2++) {
            float t = __ldg(&cb[c2]);
#pragma unroll
            for (int c1 = 0; c1 < 16; c1++)
                t = fmaf(xin[c1], __ldg(&cw[c2 * 16 + c1]), t);
            t = fmaxf(t, 0.0f);
            s_xc[c2 * CS + po] = fmaf(s_sc0[c2], t, s_sh0[c2]);
        }
    }
    __syncthreads();

    const int lane = tid & 31;
    const int wg   = tid >> 5;

    if (act) {
        // ---- d1: 1x1, 8 -> 16 ----  (8px x 2c2; pixel-pair accs)
        {
            const int prow = lane >> 1;
            const int pcol = (lane & 1) * 8;
            const int c2base = wg * 2;
            const int po = prow * RS + pcol;
            ull acc[2][4];
#pragma unroll
            for (int c2 = 0; c2 < 2; c2++) {
                ull bv = dup2(__ldg(&d1b[c2base + c2]));
                acc[c2][0] = bv; acc[c2][1] = bv; acc[c2][2] = bv; acc[c2][3] = bv;
            }
#pragma unroll
            for (int c1 = 0; c1 < 8; c1++) {
                const float* p = s_xc + c1 * CS + po;
                float4 a = *(const float4*)p;
                float4 b = *(const float4*)(p + 4);
                ull va0 = pack2(a.x, a.y), va1 = pack2(a.z, a.w);
                ull vb0 = pack2(b.x, b.y), vb1 = pack2(b.z, b.w);
#pragma unroll
                for (int c2 = 0; c2 < 2; c2++) {
                    ull w = dup2(w1s[(c2base + c2) * 8 + c1]);
                    fma2(acc[c2][0], w, va0);
                    fma2(acc[c2][1], w, va1);
                    fma2(acc[c2][2], w, vb0);
                    fma2(acc[c2][3], w, vb1);
                }
            }
#pragma unroll
            for (int c2 = 0; c2 < 2; c2++) {
                int c = c2base + c2;
                float sc = s_sc1[c], sh = s_sh1[c];
                float2 f0 = unpack2(acc[c2][0]), f1 = unpack2(acc[c2][1]);
                float2 f2 = unpack2(acc[c2][2]), f3 = unpack2(acc[c2][3]);
                float4 o0, o1;
                o0.x = fmaf(sc, fmaxf(f0.x, 0.f), sh); o0.y = fmaf(sc, fmaxf(f0.y, 0.f), sh);
                o0.z = fmaf(sc, fmaxf(f1.x, 0.f), sh); o0.w = fmaf(sc, fmaxf(f1.y, 0.f), sh);
                o1.x = fmaf(sc, fmaxf(f2.x, 0.f), sh); o1.y = fmaf(sc, fmaxf(f2.y, 0.f), sh);
                o1.z = fmaf(sc, fmaxf(f3.x, 0.f), sh); o1.w = fmaf(sc, fmaxf(f3.y, 0.f), sh);
                *(float4*)(s_a + c * CS + po)     = o0;
                *(float4*)(s_a + c * CS + po + 4) = o1;
            }
        }
        __syncthreads();

        // ---- d2: 3x3, 16 -> 16 ----  (4px x 4c2; channel-pair accs)
        {
            const int pg    = tid & 63;
            const int prow4 = pg >> 2;
            const int pcol4 = (pg & 3) * 4;
            const int pairb = (tid >> 6) * 2;   // 2 pairs of 8
            ull acc[2][4];
#pragma unroll
            for (int p = 0; p < 2; p++) {
                int c2 = 2 * (pairb + p);
                ull bv = pack2(__ldg(&d2b[c2]), __ldg(&d2b[c2 + 1]));
                acc[p][0] = bv; acc[p][1] = bv; acc[p][2] = bv; acc[p][3] = bv;
            }
            const float* sap = s_a + pcol4;
#pragma unroll 4
            for (int c1 = 0; c1 < 16; c1++) {
                const float* cbase = sap + c1 * CS;
#pragma unroll
                for (int r = 0; r < 3; r++) {
                    int yy = prow4 - 1 + r;
                    float v0, v5; float4 m;
                    if ((unsigned)yy < 16u) {
                        const float* rp = cbase + yy * RS;
                        m = *(const float4*)rp;
                        v0 = (pcol4 > 0)  ? rp[-1] : 0.f;
                        v5 = (pcol4 < 12) ? rp[4]  : 0.f;
                    } else { m = make_float4(0.f,0.f,0.f,0.f); v0 = 0.f; v5 = 0.f; }
                    ull vd[6] = {dup2(v0), dup2(m.x), dup2(m.y), dup2(m.z), dup2(m.w), dup2(v5)};
                    const float2* wrow = w2d2 + (c1 * 9 + r * 3) * 8 + pairb;
#pragma unroll
                    for (int dx = 0; dx < 3; dx++) {
                        ulonglong2 w = *(const ulonglong2*)(wrow + dx * 8);
#pragma unroll
                        for (int k = 0; k < 4; k++) {
                            fma2(acc[0][k], w.x, vd[dx + k]);
                            fma2(acc[1][k], w.y, vd[dx + k]);
                        }
                    }
                }
            }
            const int poc = prow4 * 16 + pcol4;
#pragma unroll
            for (int p = 0; p < 2; p++) {
                int c2 = 2 * (pairb + p);
                float sa = s_sc2[c2], ha = s_sh2[c2];
                float sb2 = s_sc2[c2 + 1], hb = s_sh2[c2 + 1];
                float4 oa, ob;
                float2 f;
                f = unpack2(acc[p][0]); oa.x = fmaf(sa, fmaxf(f.x,0.f), ha); ob.x = fmaf(sb2, fmaxf(f.y,0.f), hb);
                f = unpack2(acc[p][1]); oa.y = fmaf(sa, fmaxf(f.x,0.f), ha); ob.y = fmaf(sb2, fmaxf(f.y,0.f), hb);
                f = unpack2(acc[p][2]); oa.z = fmaf(sa, fmaxf(f.x,0.f), ha); ob.z = fmaf(sb2, fmaxf(f.y,0.f), hb);
                f = unpack2(acc[p][3]); oa.w = fmaf(sa, fmaxf(f.x,0.f), ha); ob.w = fmaf(sb2, fmaxf(f.y,0.f), hb);
                *(float4*)(s_b + c2 * 256 + poc)       = oa;
                *(float4*)(s_b + (c2 + 1) * 256 + poc) = ob;
            }
        }
        __syncthreads();

        // ---- d3: 1x1, 16 -> 8 ----  (coalesced quad map; pixel-pair accs)
        {
            const int q      = tid & 63;
            const int c2base = (tid >> 6) * 2;   // 2 of 8 channels
            ull acc[2][2];
#pragma unroll
            for (int c2 = 0; c2 < 2; c2++) {
                ull bv = dup2(__ldg(&d3b[c2base + c2]));
                acc[c2][0] = bv; acc[c2][1] = bv;
            }
#pragma unroll
            for (int c1 = 0; c1 < 16; c1++) {
                float4 v = *(const float4*)(s_b + c1 * 256 + q * 4);
                ull v0 = pack2(v.x, v.y), v1 = pack2(v.z, v.w);
#pragma unroll
                for (int c2 = 0; c2 < 2; c2++) {
                    ull w = dup2(w3s[(c2base + c2) * 16 + c1]);
                    fma2(acc[c2][0], w, v0);
                    fma2(acc[c2][1], w, v1);
                }
            }
#pragma unroll
            for (int c2 = 0; c2 < 2; c2++) {
                int c = c2base + c2;
                float sc = s_sc3[c], sh = s_sh3[c];
                float2 f0 = unpack2(acc[c2][0]), f1 = unpack2(acc[c2][1]);
                float4 o;
                o.x = fmaf(sc, fmaxf(f0.x, 0.f), sh);
                o.y = fmaf(sc, fmaxf(f0.y, 0.f), sh);
                o.z = fmaf(sc, fmaxf(f1.x, 0.f), sh);
                o.w = fmaf(sc, fmaxf(f1.y, 0.f), sh);
                *(float4*)(s_f + c * 256 + q * 4) = o;
            }
        }
        __syncthreads();
    }

    // fused maxpool -> g_x2p
    const float* srcp = act ? s_f : s_xc;
    const int chs = act ? 256 : CS;
    const int rs  = act ? 16 : RS;
#pragma unroll
    for (int k = 0; k < 2; k++) {
        int o = tid + k * 256;
        int c = o >> 6;
        int q = o & 63;
        int qy = q >> 3, qx = q & 7;
        const float* sp = &srcp[c * chs + (qy * 2) * rs + qx * 2];
        float mo = fmaxf(fmaxf(sp[0], sp[1]), fmaxf(sp[rs], sp[rs + 1]));
        g_x2p[((n * 8 + c) * 128 + by * 8 + qy) * 128 + (bx * 8 + qx)] = mo;
    }
}

// ---------------------------------------------------------------------------
// FC (split-K) + softmax
// ---------------------------------------------------------------------------
__global__ void fc_partial_kernel(const float* __restrict__ fc_w)
{
    const int b = blockIdx.x;       // 0..127
    const int n = b >> 3, s = b & 7;
    const int tid = threadIdx.x;
    const float* f = g_x2p + n * 131072 + s * 16384;

    float part[10];
#pragma unroll
    for (int k = 0; k < 10; k++) part[k] = 0.0f;

    for (int j = tid; j < 16384; j += 256) {
        float fv = f[j];
#pragma unroll
        for (int k = 0; k < 10; k++)
            part[k] = fmaf(fv, __ldg(&fc_w[k * 131072 + s * 16384 + j]), part[k]);
    }

    __shared__ float sred[10][256];
#pragma unroll
    for (int k = 0; k < 10; k++) sred[k][tid] = part[k];
    __syncthreads();
    for (int st = 128; st > 0; st >>= 1) {
        if (tid < st) {
#pragma unroll
            for (int k = 0; k < 10; k++) sred[k][tid] += sred[k][tid + st];
        }
        __syncthreads();
    }
    if (tid < 10) g_fcpart[(n * 8 + s) * 10 + tid] = sred[tid][0];
}

__global__ void fc_final_kernel(const float* __restrict__ fc_b, float* __restrict__ out)
{
    const int t = threadIdx.x;
    __shared__ float s_l[16][10];
    if (t < 160) {
        int n = t / 10, k = t - n * 10;
        float a = fc_b[k];
#pragma unroll
        for (int s = 0; s < 8; s++) a += g_fcpart[(n * 8 + s) * 10 + k];
        s_l[n][k] = a;
    }
    __syncthreads();
    if (t < 16) {
        float mx = -1e30f;
#pragma unroll
        for (int k = 0; k < 10; k++) mx = fmaxf(mx, s_l[t][k]);
        float e[10], se = 0.f;
#pragma unroll
        for (int k = 0; k < 10; k++) { e[k] = expf(s_l[t][k] - mx); se += e[k]; }
        float inv = 1.0f / se;
#pragma unroll
        for (int k = 0; k < 10; k++) out[t * 10 + k] = e[k] * inv;
    }
}

// ---------------------------------------------------------------------------
extern "C" void kernel_launch(void* const* d_in, const int* in_sizes, int n_in,
                              void* d_out, int out_size)
{
    const float* x      = (const float*)d_in[0];
    const float* mask   = (const float*)d_in[1];
    const float* s1_cw  = (const float*)d_in[2];
    const float* s1_cb  = (const float*)d_in[3];
    const float* s1_bn0 = (const float*)d_in[4];
    const float* s1_d1w = (const float*)d_in[5];
    const float* s1_d1b = (const float*)d_in[6];
    const float* s1_bn1 = (const float*)d_in[7];
    const float* s1_d2w = (const float*)d_in[8];
    const float* s1_d2b = (const float*)d_in[9];
    const float* s1_bn2 = (const float*)d_in[10];
    const float* s1_d3w = (const float*)d_in[11];
    const float* s1_d3b = (const float*)d_in[12];
    const float* s1_bn3 = (const float*)d_in[13];
    const float* s2_cw  = (const float*)d_in[14];
    const float* s2_cb  = (const float*)d_in[15];
    const float* s2_bn0 = (const float*)d_in[16];
    const float* s2_d1w = (const float*)d_in[17];
    const float* s2_d1b = (const float*)d_in[18];
    const float* s2_bn1 = (const float*)d_in[19];
    const float* s2_d2w = (const float*)d_in[20];
    const float* s2_d2b = (const float*)d_in[21];
    const float* s2_bn2 = (const float*)d_in[22];
    const float* s2_d3w = (const float*)d_in[23];
    const float* s2_d3b = (const float*)d_in[24];
    const float* s2_bn3 = (const float*)d_in[25];
    const float* fc_w   = (const float*)d_in[26];
    const float* fc_b   = (const float*)d_in[27];

    const int smem1 = 28672 * sizeof(float);   // 112 KB dynamic
    cudaFuncSetAttribute(stage1_kernel, cudaFuncAttributeMaxDynamicSharedMemorySize, smem1);
    const int smem2 = 11776 * sizeof(float);   // 46 KB dynamic
    cudaFuncSetAttribute(stage2_kernel, cudaFuncAttributeMaxDynamicSharedMemorySize, smem2);

    stage1_kernel<<<16 * 32 * 32, 256, smem1>>>(
        x, mask, s1_cw, s1_cb, s1_bn0, s1_d1w, s1_d1b, s1_bn1,
        s1_d2w, s1_d2b, s1_bn2, s1_d3w, s1_d3b, s1_bn3);

    stage2_kernel<<<16 * 16 * 16, 256, smem2>>>(
        s2_cw, s2_cb, s2_bn0, s2_d1w, s2_d1b, s2_bn1,
        s2_d2w, s2_d2b, s2_bn2, s2_d3w, s2_d3b, s2_bn3);

    fc_partial_kernel<<<128, 256>>>(fc_w);
    fc_final_kernel<<<1, 256>>>(fc_b, (float*)d_out);
}

// round 4
// speedup vs baseline: 1.2621x; 1.2621x over previous
#include <cuda_runtime.h>

#define EPSV 1e-5f

// scratch (no cudaMalloc allowed)
__device__ float g_x1p[16 * 16 * 256 * 256];   // stage1 output, pooled  [N,16,256,256]
__device__ float g_mask2[16 * 256 * 256];      // pooled mask            [N,256,256]
__device__ float g_x2p[16 * 8 * 128 * 128];    // stage2 output, pooled  [N,8,128,128]
__device__ float g_fcpart[16 * 8 * 10];        // FC partial sums

// prepped weights / BN (global; read warp-uniform via L1)
__device__ __align__(16) float g_w2p[9216];    // stage1 d2 paired [c1*9+t][pair16][2]
__device__ __align__(16) float g_q2p[2304];    // stage2 d2 paired [c1*9+t][pair8][2]
__device__ float g_sc[144], g_sh[144];
// offsets: s1bn0=0(16) s1bn1=16(32) s1bn2=48(32) s1bn3=80(16)
//          s2bn0=96(8) s2bn1=104(16) s2bn2=120(16) s2bn3=136(8)

typedef unsigned long long ull;

__device__ __forceinline__ void fma2(ull& d, ull a, ull b) {
    asm("fma.rn.f32x2 %0, %1, %2, %0;" : "+l"(d) : "l"(a), "l"(b));
}
__device__ __forceinline__ ull pack2(float lo, float hi) {
    ull r; asm("mov.b64 %0, {%1, %2};" : "=l"(r) : "f"(lo), "f"(hi)); return r;
}
__device__ __forceinline__ ull dup2(float v) { return pack2(v, v); }
__device__ __forceinline__ float2 unpack2(ull u) {
    float2 f; asm("mov.b64 {%0, %1}, %2;" : "=f"(f.x), "=f"(f.y) : "l"(u)); return f;
}

// padded row stride (floats) for activation tiles
#define RS 20
#define CS 320   // 16 rows * RS

// ---------------------------------------------------------------------------
// prep: reorder d2 weights to paired layout + BN affine precompute
// ---------------------------------------------------------------------------
__global__ void prep_kernel(
    const float* __restrict__ s1d2w, const float* __restrict__ s2d2w,
    const float* __restrict__ b10, const float* __restrict__ b11,
    const float* __restrict__ b12, const float* __restrict__ b13,
    const float* __restrict__ b20, const float* __restrict__ b21,
    const float* __restrict__ b22, const float* __restrict__ b23)
{
    const int tid = threadIdx.x;
    for (int i = tid; i < 9216; i += 256) {
        int c2 = i / 288, rem = i - c2 * 288;
        int c1 = rem / 9, t = rem - c1 * 9;
        g_w2p[((c1 * 9 + t) * 16 + (c2 >> 1)) * 2 + (c2 & 1)] = s1d2w[i];
    }
    for (int i = tid; i < 2304; i += 256) {
        int c2 = i / 144, rem = i - c2 * 144;
        int c1 = rem / 9, t = rem - c1 * 9;
        g_q2p[((c1 * 9 + t) * 8 + (c2 >> 1)) * 2 + (c2 & 1)] = s2d2w[i];
    }
    if (tid < 144) {
        const float* bp; int c, C;
        if      (tid < 16)  { bp = b10; c = tid;       C = 16; }
        else if (tid < 48)  { bp = b11; c = tid - 16;  C = 32; }
        else if (tid < 80)  { bp = b12; c = tid - 48;  C = 32; }
        else if (tid < 96)  { bp = b13; c = tid - 80;  C = 16; }
        else if (tid < 104) { bp = b20; c = tid - 96;  C = 8;  }
        else if (tid < 120) { bp = b21; c = tid - 104; C = 16; }
        else if (tid < 136) { bp = b22; c = tid - 120; C = 16; }
        else                { bp = b23; c = tid - 136; C = 8;  }
        float g = bp[c], b = bp[C + c], m = bp[2 * C + c], v = bp[3 * C + c];
        float s = g * rsqrtf(v + EPSV);
        g_sc[tid] = s; g_sh[tid] = b - s * m;
    }
}

// ---------------------------------------------------------------------------
// Stage 1: x[16,3,512,512] -> g_x1p[16,16,256,256], mask -> g_mask2
// SMEM (floats): s_a [0..10240) padded 32xCS (d3-out flat 16x256 aliases);
//                s_b [10240..18432) compact 32x256 (s_xc padded 16xCS aliases)
// ---------------------------------------------------------------------------
__global__ void __launch_bounds__(256, 2) stage1_kernel(
    const float* __restrict__ x, const float* __restrict__ mask,
    const float* __restrict__ cw, const float* __restrict__ cb,
    const float* __restrict__ d1w, const float* __restrict__ d1b,
    const float* __restrict__ d2b,
    const float* __restrict__ d3w, const float* __restrict__ d3b)
{
    extern __shared__ float sm[];
    float*  s_a   = sm;                  // padded [32][CS]
    float*  s_f   = sm;                  // d3 out flat [16][256]
    float*  s_b   = sm + 10240;          // compact [32][256]
    float*  s_xc  = s_b;                 // padded [16][CS] alias

    __shared__ float s_red[256];
    __shared__ float s_wsum[8];
    __shared__ int s_active;

    const int bid = blockIdx.x;
    const int n   = bid >> 10;
    const int by  = (bid >> 5) & 31;
    const int bx  = bid & 31;
    const int tid = threadIdx.x;
    const int py  = tid >> 4, px_ = tid & 15;
    const int gy  = by * 16 + py, gx = bx * 16 + px_;

    // mask tile + activity
    float mval = mask[(n * 512 + gy) * 512 + gx];
    s_red[tid] = mval;
    float msum = mval;
#pragma unroll
    for (int o = 16; o; o >>= 1) msum += __shfl_xor_sync(0xffffffffu, msum, o);
    if ((tid & 31) == 0) s_wsum[tid >> 5] = msum;
    __syncthreads();

    if (tid < 64) {
        int qy = tid >> 3, qx = tid & 7;
        int p0 = (qy * 2) * 16 + qx * 2;
        float m0 = fmaxf(fmaxf(s_red[p0], s_red[p0 + 1]),
                         fmaxf(s_red[p0 + 16], s_red[p0 + 17]));
        g_mask2[(n * 256 + by * 8 + qy) * 256 + (bx * 8 + qx)] = m0;
    }
    if (tid == 0) {
        float t = 0.f;
#pragma unroll
        for (int i = 0; i < 8; i++) t += s_wsum[i];
        s_active = (t > 128.0f) ? 1 : 0;
    }

    // channel path: 1x1 conv 3->16 + bias, relu, bn  -> s_xc (padded)
    {
        const int ibase = ((n * 3) * 512 + gy) * 512 + gx;
        float xv0 = x[ibase];
        float xv1 = x[ibase + 512 * 512];
        float xv2 = x[ibase + 2 * 512 * 512];
        const int po = py * RS + px_;
#pragma unroll
        for (int c = 0; c < 16; c++) {
            float t = __ldg(&cw[c * 3 + 0]) * xv0 + __ldg(&cw[c * 3 + 1]) * xv1 +
                      __ldg(&cw[c * 3 + 2]) * xv2 + __ldg(&cb[c]);
            t = fmaxf(t, 0.0f);
            s_xc[c * CS + po] = fmaf(__ldg(&g_sc[c]), t, __ldg(&g_sh[c]));
        }
    }
    __syncthreads();   // s_xc + s_active visible

    const int act = s_active;

    // thread maps
    const int lane  = tid & 31;
    const int prow  = lane >> 1;          // 0..15
    const int pcol  = (lane & 1) * 8;     // 0 or 8
    const int wg    = tid >> 5;           // warp id 0..7

    if (act) {
        // ---- d1: 1x1, 16 -> 32 ----  (8px x 4c2 per thread; pixel-pair accs)
        {
            const int c2base = wg * 4;
            ull acc[4][4];
#pragma unroll
            for (int c2 = 0; c2 < 4; c2++) {
                ull bv = dup2(__ldg(&d1b[c2base + c2]));
                acc[c2][0] = bv; acc[c2][1] = bv; acc[c2][2] = bv; acc[c2][3] = bv;
            }
            const int po = prow * RS + pcol;
#pragma unroll
            for (int c1 = 0; c1 < 16; c1++) {
                const float* p = s_xc + c1 * CS + po;
                float4 a = *(const float4*)p;
                float4 b = *(const float4*)(p + 4);
                ull va0 = pack2(a.x, a.y), va1 = pack2(a.z, a.w);
                ull vb0 = pack2(b.x, b.y), vb1 = pack2(b.z, b.w);
#pragma unroll
                for (int c2 = 0; c2 < 4; c2++) {
                    ull w = dup2(__ldg(&d1w[(c2base + c2) * 16 + c1]));
                    fma2(acc[c2][0], w, va0);
                    fma2(acc[c2][1], w, va1);
                    fma2(acc[c2][2], w, vb0);
                    fma2(acc[c2][3], w, vb1);
                }
            }
#pragma unroll
            for (int c2 = 0; c2 < 4; c2++) {
                int c = c2base + c2;
                float sc = __ldg(&g_sc[16 + c]), sh = __ldg(&g_sh[16 + c]);
                float4 o0, o1;
                float2 f0 = unpack2(acc[c2][0]), f1 = unpack2(acc[c2][1]);
                float2 f2 = unpack2(acc[c2][2]), f3 = unpack2(acc[c2][3]);
                o0.x = fmaf(sc, fmaxf(f0.x, 0.f), sh); o0.y = fmaf(sc, fmaxf(f0.y, 0.f), sh);
                o0.z = fmaf(sc, fmaxf(f1.x, 0.f), sh); o0.w = fmaf(sc, fmaxf(f1.y, 0.f), sh);
                o1.x = fmaf(sc, fmaxf(f2.x, 0.f), sh); o1.y = fmaf(sc, fmaxf(f2.y, 0.f), sh);
                o1.z = fmaf(sc, fmaxf(f3.x, 0.f), sh); o1.w = fmaf(sc, fmaxf(f3.y, 0.f), sh);
                *(float4*)(s_a + c * CS + po)     = o0;
                *(float4*)(s_a + c * CS + po + 4) = o1;
            }
        }
        __syncthreads();

        // ---- d2: 3x3 (block-padded), 32 -> 32 ----  (8px x 4c2; channel-pair accs)
        {
            const int pairb = wg * 2;            // pairs (c2 = 2*pairb .. 2*pairb+3)
            ull acc[2][8];
#pragma unroll
            for (int p = 0; p < 2; p++) {
                int c2 = 2 * (pairb + p);
                ull bv = pack2(__ldg(&d2b[c2]), __ldg(&d2b[c2 + 1]));
#pragma unroll
                for (int k = 0; k < 8; k++) acc[p][k] = bv;
            }
            const float* sap = s_a + pcol;
            const ulonglong2* __restrict__ wbase =
                (const ulonglong2*)g_w2p + pairb / 2;   // 2 pairs per ulonglong2
#pragma unroll 4
            for (int c1 = 0; c1 < 32; c1++) {
                const float* cbase = sap + c1 * CS;
#pragma unroll
                for (int r = 0; r < 3; r++) {
                    int yy = prow - 1 + r;
                    float u0, u9; float4 m1, m2;
                    if ((unsigned)yy < 16u) {
                        const float* rp = cbase + yy * RS;
                        m1 = *(const float4*)rp;
                        m2 = *(const float4*)(rp + 4);
                        u0 = pcol ? rp[-1] : 0.f;
                        u9 = pcol ? 0.f : rp[8];
                    } else {
                        m1 = make_float4(0.f, 0.f, 0.f, 0.f);
                        m2 = m1; u0 = 0.f; u9 = 0.f;
                    }
                    ull vd[10] = {dup2(u0), dup2(m1.x), dup2(m1.y), dup2(m1.z), dup2(m1.w),
                                  dup2(m2.x), dup2(m2.y), dup2(m2.z), dup2(m2.w), dup2(u9)};
                    const ulonglong2* wrow = wbase + (c1 * 9 + r * 3) * 8;  // 16 pairs = 8 ull2
#pragma unroll
                    for (int dx = 0; dx < 3; dx++) {
                        ulonglong2 w = __ldg(wrow + dx * 8);
#pragma unroll
                        for (int k = 0; k < 8; k++) {
                            fma2(acc[0][k], w.x, vd[dx + k]);
                            fma2(acc[1][k], w.y, vd[dx + k]);
                        }
                    }
                }
            }
            // epilogue -> s_b compact (overwrites s_xc alias; d1 reads done)
            const int poc = prow * 16 + pcol;
#pragma unroll
            for (int p = 0; p < 2; p++) {
                int c2 = 2 * (pairb + p);
                float sa = __ldg(&g_sc[48 + c2]), ha = __ldg(&g_sh[48 + c2]);
                float sb2 = __ldg(&g_sc[48 + c2 + 1]), hb = __ldg(&g_sh[48 + c2 + 1]);
                float4 oa0, oa1, ob0, ob1;
                float2 f;
                f = unpack2(acc[p][0]); oa0.x = fmaf(sa, fmaxf(f.x,0.f), ha); ob0.x = fmaf(sb2, fmaxf(f.y,0.f), hb);
                f = unpack2(acc[p][1]); oa0.y = fmaf(sa, fmaxf(f.x,0.f), ha); ob0.y = fmaf(sb2, fmaxf(f.y,0.f), hb);
                f = unpack2(acc[p][2]); oa0.z = fmaf(sa, fmaxf(f.x,0.f), ha); ob0.z = fmaf(sb2, fmaxf(f.y,0.f), hb);
                f = unpack2(acc[p][3]); oa0.w = fmaf(sa, fmaxf(f.x,0.f), ha); ob0.w = fmaf(sb2, fmaxf(f.y,0.f), hb);
                f = unpack2(acc[p][4]); oa1.x = fmaf(sa, fmaxf(f.x,0.f), ha); ob1.x = fmaf(sb2, fmaxf(f.y,0.f), hb);
                f = unpack2(acc[p][5]); oa1.y = fmaf(sa, fmaxf(f.x,0.f), ha); ob1.y = fmaf(sb2, fmaxf(f.y,0.f), hb);
                f = unpack2(acc[p][6]); oa1.z = fmaf(sa, fmaxf(f.x,0.f), ha); ob1.z = fmaf(sb2, fmaxf(f.y,0.f), hb);
                f = unpack2(acc[p][7]); oa1.w = fmaf(sa, fmaxf(f.x,0.f), ha); ob1.w = fmaf(sb2, fmaxf(f.y,0.f), hb);
                *(float4*)(s_b + c2 * 256 + poc)           = oa0;
                *(float4*)(s_b + c2 * 256 + poc + 4)       = oa1;
                *(float4*)(s_b + (c2 + 1) * 256 + poc)     = ob0;
                *(float4*)(s_b + (c2 + 1) * 256 + poc + 4) = ob1;
            }
        }
        __syncthreads();

        // ---- d3: 1x1, 32 -> 16 ----  (coalesced quad map; pixel-pair accs)
        {
            const int q      = tid & 63;         // pixel quad
            const int c2base = (tid >> 6) * 4;   // 4 of 16 channels
            ull acc[4][2];
#pragma unroll
            for (int c2 = 0; c2 < 4; c2++) {
                ull bv = dup2(__ldg(&d3b[c2base + c2]));
                acc[c2][0] = bv; acc[c2][1] = bv;
            }
#pragma unroll 4
            for (int c1 = 0; c1 < 32; c1++) {
                float4 v = *(const float4*)(s_b + c1 * 256 + q * 4);
                ull v0 = pack2(v.x, v.y), v1 = pack2(v.z, v.w);
#pragma unroll
                for (int c2 = 0; c2 < 4; c2++) {
                    ull w = dup2(__ldg(&d3w[(c2base + c2) * 32 + c1]));
                    fma2(acc[c2][0], w, v0);
                    fma2(acc[c2][1], w, v1);
                }
            }
#pragma unroll
            for (int c2 = 0; c2 < 4; c2++) {
                int c = c2base + c2;
                float sc = __ldg(&g_sc[80 + c]), sh = __ldg(&g_sh[80 + c]);
                float2 f0 = unpack2(acc[c2][0]), f1 = unpack2(acc[c2][1]);
                float4 o;
                o.x = fmaf(sc, fmaxf(f0.x, 0.f), sh);
                o.y = fmaf(sc, fmaxf(f0.y, 0.f), sh);
                o.z = fmaf(sc, fmaxf(f1.x, 0.f), sh);
                o.w = fmaf(sc, fmaxf(f1.y, 0.f), sh);
                *(float4*)(s_f + c * 256 + q * 4) = o;
            }
        }
        __syncthreads();
    }

    // fused 2x2 maxpool -> g_x1p
    const float* srcp = act ? s_f : s_xc;
    const int chs = act ? 256 : CS;
    const int rs  = act ? 16 : RS;
#pragma unroll
    for (int k = 0; k < 4; k++) {
        int o = tid + k * 256;
        int c = o >> 6;
        int q = o & 63;
        int qy = q >> 3, qx = q & 7;
        const float* sp = &srcp[c * chs + (qy * 2) * rs + qx * 2];
        float mo = fmaxf(fmaxf(sp[0], sp[1]), fmaxf(sp[rs], sp[rs + 1]));
        g_x1p[((n * 16 + c) * 256 + by * 8 + qy) * 256 + (bx * 8 + qx)] = mo;
    }
}

// ---------------------------------------------------------------------------
// Stage 2: g_x1p[16,16,256,256] -> g_x2p[16,8,128,128]
// SMEM (floats): s_a [0..5120) padded 16xCS (d3-out flat 8x256 aliases);
//                s_b [5120..9216) compact 16x256 (s_xc padded 8xCS aliases)
// ---------------------------------------------------------------------------
__global__ void __launch_bounds__(256, 2) stage2_kernel(
    const float* __restrict__ cw, const float* __restrict__ cb,
    const float* __restrict__ d1w, const float* __restrict__ d1b,
    const float* __restrict__ d2b,
    const float* __restrict__ d3w, const float* __restrict__ d3b)
{
    extern __shared__ float sm2[];
    float*  s_a   = sm2;
    float*  s_f   = sm2;
    float*  s_b   = sm2 + 5120;
    float*  s_xc  = s_b;

    __shared__ float s_wsum[8];
    __shared__ int s_active;

    const int bid = blockIdx.x;
    const int n   = bid >> 8;
    const int by  = (bid >> 4) & 15;
    const int bx  = bid & 15;
    const int tid = threadIdx.x;
    const int py  = tid >> 4, px_ = tid & 15;
    const int gy  = by * 16 + py, gx = bx * 16 + px_;

    {
        float mv = g_mask2[(n * 256 + gy) * 256 + gx];
#pragma unroll
        for (int o = 16; o; o >>= 1) mv += __shfl_xor_sync(0xffffffffu, mv, o);
        if ((tid & 31) == 0) s_wsum[tid >> 5] = mv;
    }
    __syncthreads();
    if (tid == 0) {
        float t = 0.f;
#pragma unroll
        for (int i = 0; i < 8; i++) t += s_wsum[i];
        s_active = (t > 128.0f) ? 1 : 0;
    }

    // channel path: 1x1 conv 16->8 -> s_xc (padded)
    {
        const int ibase = ((n * 16) * 256 + gy) * 256 + gx;
        float xin[16];
#pragma unroll
        for (int c = 0; c < 16; c++) xin[c] = g_x1p[ibase + c * 65536];
        const int po = py * RS + px_;
#pragma unroll
        for (int c2 = 0; c2 < 8; c2++) {
            float t = __ldg(&cb[c2]);
#pragma unroll
            for (int c1 = 0; c1 < 16; c1++)
                t = fmaf(xin[c1], __ldg(&cw[c2 * 16 + c1]), t);
            t = fmaxf(t, 0.0f);
            s_xc[c2 * CS + po] = fmaf(__ldg(&g_sc[96 + c2]), t, __ldg(&g_sh[96 + c2]));
        }
    }
    __syncthreads();

    const int act  = s_active;
    const int lane = tid & 31;
    const int wg   = tid >> 5;

    if (act) {
        // ---- d1: 1x1, 8 -> 16 ----  (8px x 2c2; pixel-pair accs)
        {
            const int prow = lane >> 1;
            const int pcol = (lane & 1) * 8;
            const int c2base = wg * 2;
            const int po = prow * RS + pcol;
            ull acc[2][4];
#pragma unroll
            for (int c2 = 0; c2 < 2; c2++) {
                ull bv = dup2(__ldg(&d1b[c2base + c2]));
                acc[c2][0] = bv; acc[c2][1] = bv; acc[c2][2] = bv; acc[c2][3] = bv;
            }
#pragma unroll
            for (int c1 = 0; c1 < 8; c1++) {
                const float* p = s_xc + c1 * CS + po;
                float4 a = *(const float4*)p;
                float4 b = *(const float4*)(p + 4);
                ull va0 = pack2(a.x, a.y), va1 = pack2(a.z, a.w);
                ull vb0 = pack2(b.x, b.y), vb1 = pack2(b.z, b.w);
#pragma unroll
                for (int c2 = 0; c2 < 2; c2++) {
                    ull w = dup2(__ldg(&d1w[(c2base + c2) * 8 + c1]));
                    fma2(acc[c2][0], w, va0);
                    fma2(acc[c2][1], w, va1);
                    fma2(acc[c2][2], w, vb0);
                    fma2(acc[c2][3], w, vb1);
                }
            }
#pragma unroll
            for (int c2 = 0; c2 < 2; c2++) {
                int c = c2base + c2;
                float sc = __ldg(&g_sc[104 + c]), sh = __ldg(&g_sh[104 + c]);
                float2 f0 = unpack2(acc[c2][0]), f1 = unpack2(acc[c2][1]);
                float2 f2 = unpack2(acc[c2][2]), f3 = unpack2(acc[c2][3]);
                float4 o0, o1;
                o0.x = fmaf(sc, fmaxf(f0.x, 0.f), sh); o0.y = fmaf(sc, fmaxf(f0.y, 0.f), sh);
                o0.z = fmaf(sc, fmaxf(f1.x, 0.f), sh); o0.w = fmaf(sc, fmaxf(f1.y, 0.f), sh);
                o1.x = fmaf(sc, fmaxf(f2.x, 0.f), sh); o1.y = fmaf(sc, fmaxf(f2.y, 0.f), sh);
                o1.z = fmaf(sc, fmaxf(f3.x, 0.f), sh); o1.w = fmaf(sc, fmaxf(f3.y, 0.f), sh);
                *(float4*)(s_a + c * CS + po)     = o0;
                *(float4*)(s_a + c * CS + po + 4) = o1;
            }
        }
        __syncthreads();

        // ---- d2: 3x3, 16 -> 16 ----  (4px x 4c2; channel-pair accs)
        {
            const int pg    = tid & 63;
            const int prow4 = pg >> 2;
            const int pcol4 = (pg & 3) * 4;
            const int pairb = (tid >> 6) * 2;   // 2 pairs of 8
            ull acc[2][4];
#pragma unroll
            for (int p = 0; p < 2; p++) {
                int c2 = 2 * (pairb + p);
                ull bv = pack2(__ldg(&d2b[c2]), __ldg(&d2b[c2 + 1]));
                acc[p][0] = bv; acc[p][1] = bv; acc[p][2] = bv; acc[p][3] = bv;
            }
            const float* sap = s_a + pcol4;
            const ulonglong2* __restrict__ wbase =
                (const ulonglong2*)g_q2p + pairb / 2;
#pragma unroll 4
            for (int c1 = 0; c1 < 16; c1++) {
                const float* cbase = sap + c1 * CS;
#pragma unroll
                for (int r = 0; r < 3; r++) {
                    int yy = prow4 - 1 + r;
                    float v0, v5; float4 m;
                    if ((unsigned)yy < 16u) {
                        const float* rp = cbase + yy * RS;
                        m = *(const float4*)rp;
                        v0 = (pcol4 > 0)  ? rp[-1] : 0.f;
                        v5 = (pcol4 < 12) ? rp[4]  : 0.f;
                    } else { m = make_float4(0.f,0.f,0.f,0.f); v0 = 0.f; v5 = 0.f; }
                    ull vd[6] = {dup2(v0), dup2(m.x), dup2(m.y), dup2(m.z), dup2(m.w), dup2(v5)};
                    const ulonglong2* wrow = wbase + (c1 * 9 + r * 3) * 4;  // 8 pairs = 4 ull2
#pragma unroll
                    for (int dx = 0; dx < 3; dx++) {
                        ulonglong2 w = __ldg(wrow + dx * 4);
#pragma unroll
                        for (int k = 0; k < 4; k++) {
                            fma2(acc[0][k], w.x, vd[dx + k]);
                            fma2(acc[1][k], w.y, vd[dx + k]);
                        }
                    }
                }
            }
            const int poc = prow4 * 16 + pcol4;
#pragma unroll
            for (int p = 0; p < 2; p++) {
                int c2 = 2 * (pairb + p);
                float sa = __ldg(&g_sc[120 + c2]), ha = __ldg(&g_sh[120 + c2]);
                float sb2 = __ldg(&g_sc[120 + c2 + 1]), hb = __ldg(&g_sh[120 + c2 + 1]);
                float4 oa, ob;
                float2 f;
                f = unpack2(acc[p][0]); oa.x = fmaf(sa, fmaxf(f.x,0.f), ha); ob.x = fmaf(sb2, fmaxf(f.y,0.f), hb);
                f = unpack2(acc[p][1]); oa.y = fmaf(sa, fmaxf(f.x,0.f), ha); ob.y = fmaf(sb2, fmaxf(f.y,0.f), hb);
                f = unpack2(acc[p][2]); oa.z = fmaf(sa, fmaxf(f.x,0.f), ha); ob.z = fmaf(sb2, fmaxf(f.y,0.f), hb);
                f = unpack2(acc[p][3]); oa.w = fmaf(sa, fmaxf(f.x,0.f), ha); ob.w = fmaf(sb2, fmaxf(f.y,0.f), hb);
                *(float4*)(s_b + c2 * 256 + poc)       = oa;
                *(float4*)(s_b + (c2 + 1) * 256 + poc) = ob;
            }
        }
        __syncthreads();

        // ---- d3: 1x1, 16 -> 8 ----  (coalesced quad map; pixel-pair accs)
        {
            const int q      = tid & 63;
            const int c2base = (tid >> 6) * 2;   // 2 of 8 channels
            ull acc[2][2];
#pragma unroll
            for (int c2 = 0; c2 < 2; c2++) {
                ull bv = dup2(__ldg(&d3b[c2base + c2]));
                acc[c2][0] = bv; acc[c2][1] = bv;
            }
#pragma unroll
            for (int c1 = 0; c1 < 16; c1++) {
                float4 v = *(const float4*)(s_b + c1 * 256 + q * 4);
                ull v0 = pack2(v.x, v.y), v1 = pack2(v.z, v.w);
#pragma unroll
                for (int c2 = 0; c2 < 2; c2++) {
                    ull w = dup2(__ldg(&d3w[(c2base + c2) * 16 + c1]));
                    fma2(acc[c2][0], w, v0);
                    fma2(acc[c2][1], w, v1);
                }
            }
#pragma unroll
            for (int c2 = 0; c2 < 2; c2++) {
                int c = c2base + c2;
                float sc = __ldg(&g_sc[136 + c]), sh = __ldg(&g_sh[136 + c]);
                float2 f0 = unpack2(acc[c2][0]), f1 = unpack2(acc[c2][1]);
                float4 o;
                o.x = fmaf(sc, fmaxf(f0.x, 0.f), sh);
                o.y = fmaf(sc, fmaxf(f0.y, 0.f), sh);
                o.z = fmaf(sc, fmaxf(f1.x, 0.f), sh);
                o.w = fmaf(sc, fmaxf(f1.y, 0.f), sh);
                *(float4*)(s_f + c * 256 + q * 4) = o;
            }
        }
        __syncthreads();
    }

    // fused maxpool -> g_x2p
    const float* srcp = act ? s_f : s_xc;
    const int chs = act ? 256 : CS;
    const int rs  = act ? 16 : RS;
#pragma unroll
    for (int k = 0; k < 2; k++) {
        int o = tid + k * 256;
        int c = o >> 6;
        int q = o & 63;
        int qy = q >> 3, qx = q & 7;
        const float* sp = &srcp[c * chs + (qy * 2) * rs + qx * 2];
        float mo = fmaxf(fmaxf(sp[0], sp[1]), fmaxf(sp[rs], sp[rs + 1]));
        g_x2p[((n * 8 + c) * 128 + by * 8 + qy) * 128 + (bx * 8 + qx)] = mo;
    }
}

// ---------------------------------------------------------------------------
// FC (split-K) + softmax
// ---------------------------------------------------------------------------
__global__ void fc_partial_kernel(const float* __restrict__ fc_w)
{
    const int b = blockIdx.x;       // 0..127
    const int n = b >> 3, s = b & 7;
    const int tid = threadIdx.x;
    const float* f = g_x2p + n * 131072 + s * 16384;

    float part[10];
#pragma unroll
    for (int k = 0; k < 10; k++) part[k] = 0.0f;

    for (int j = tid; j < 16384; j += 256) {
        float fv = f[j];
#pragma unroll
        for (int k = 0; k < 10; k++)
            part[k] = fmaf(fv, __ldg(&fc_w[k * 131072 + s * 16384 + j]), part[k]);
    }

    __shared__ float sred[10][256];
#pragma unroll
    for (int k = 0; k < 10; k++) sred[k][tid] = part[k];
    __syncthreads();
    for (int st = 128; st > 0; st >>= 1) {
        if (tid < st) {
#pragma unroll
            for (int k = 0; k < 10; k++) sred[k][tid] += sred[k][tid + st];
        }
        __syncthreads();
    }
    if (tid < 10) g_fcpart[(n * 8 + s) * 10 + tid] = sred[tid][0];
}

__global__ void fc_final_kernel(const float* __restrict__ fc_b, float* __restrict__ out)
{
    const int t = threadIdx.x;
    __shared__ float s_l[16][10];
    if (t < 160) {
        int n = t / 10, k = t - n * 10;
        float a = fc_b[k];
#pragma unroll
        for (int s = 0; s < 8; s++) a += g_fcpart[(n * 8 + s) * 10 + k];
        s_l[n][k] = a;
    }
    __syncthreads();
    if (t < 16) {
        float mx = -1e30f;
#pragma unroll
        for (int k = 0; k < 10; k++) mx = fmaxf(mx, s_l[t][k]);
        float e[10], se = 0.f;
#pragma unroll
        for (int k = 0; k < 10; k++) { e[k] = expf(s_l[t][k] - mx); se += e[k]; }
        float inv = 1.0f / se;
#pragma unroll
        for (int k = 0; k < 10; k++) out[t * 10 + k] = e[k] * inv;
    }
}

// ---------------------------------------------------------------------------
extern "C" void kernel_launch(void* const* d_in, const int* in_sizes, int n_in,
                              void* d_out, int out_size)
{
    const float* x      = (const float*)d_in[0];
    const float* mask   = (const float*)d_in[1];
    const float* s1_cw  = (const float*)d_in[2];
    const float* s1_cb  = (const float*)d_in[3];
    const float* s1_bn0 = (const float*)d_in[4];
    const float* s1_d1w = (const float*)d_in[5];
    const float* s1_d1b = (const float*)d_in[6];
    const float* s1_bn1 = (const float*)d_in[7];
    const float* s1_d2w = (const float*)d_in[8];
    const float* s1_d2b = (const float*)d_in[9];
    const float* s1_bn2 = (const float*)d_in[10];
    const float* s1_d3w = (const float*)d_in[11];
    const float* s1_d3b = (const float*)d_in[12];
    const float* s1_bn3 = (const float*)d_in[13];
    const float* s2_cw  = (const float*)d_in[14];
    const float* s2_cb  = (const float*)d_in[15];
    const float* s2_bn0 = (const float*)d_in[16];
    const float* s2_d1w = (const float*)d_in[17];
    const float* s2_d1b = (const float*)d_in[18];
    const float* s2_bn1 = (const float*)d_in[19];
    const float* s2_d2w = (const float*)d_in[20];
    const float* s2_d2b = (const float*)d_in[21];
    const float* s2_bn2 = (const float*)d_in[22];
    const float* s2_d3w = (const float*)d_in[23];
    const float* s2_d3b = (const float*)d_in[24];
    const float* s2_bn3 = (const float*)d_in[25];
    const float* fc_w   = (const float*)d_in[26];
    const float* fc_b   = (const float*)d_in[27];

    prep_kernel<<<1, 256>>>(s1_d2w, s2_d2w,
                            s1_bn0, s1_bn1, s1_bn2, s1_bn3,
                            s2_bn0, s2_bn1, s2_bn2, s2_bn3);

    const int smem1 = 18432 * sizeof(float);   // 72 KB dynamic
    cudaFuncSetAttribute(stage1_kernel, cudaFuncAttributeMaxDynamicSharedMemorySize, smem1);
    const int smem2 = 9216 * sizeof(float);    // 36 KB dynamic
    cudaFuncSetAttribute(stage2_kernel, cudaFuncAttributeMaxDynamicSharedMemorySize, smem2);

    stage1_kernel<<<16 * 32 * 32, 256, smem1>>>(
        x, mask, s1_cw, s1_cb, s1_d1w, s1_d1b, s1_d2b, s1_d3w, s1_d3b);

    stage2_kernel<<<16 * 16 * 16, 256, smem2>>>(
        s2_cw, s2_cb, s2_d1w, s2_d1b, s2_d2b, s2_d3w, s2_d3b);

    fc_partial_kernel<<<128, 256>>>(fc_w);
    fc_final_kernel<<<1, 256>>>(fc_b, (float*)d_out);
}

// round 5
// speedup vs baseline: 1.3379x; 1.0600x over previous
#include <cuda_runtime.h>

#define EPSV 1e-5f

// scratch (no cudaMalloc allowed)
__device__ float g_x1p[16 * 16 * 256 * 256];   // stage1 output, pooled  [N,16,256,256]
__device__ float g_mask2[16 * 256 * 256];      // pooled mask            [N,256,256]
__device__ float g_x2p[16 * 8 * 128 * 128];    // stage2 output, pooled  [N,8,128,128]
__device__ float g_fcpart[16 * 32 * 10];       // FC partial sums
__device__ int   g_cnt1;                       // active tile count (stage1)
__device__ int   g_list1[16384];               // active tile list  (stage1)

// prepped weights / BN (global; read warp-uniform via L1)
__device__ __align__(16) float g_w2p[9216];    // stage1 d2 paired [c1*9+t][pair16][2]
__device__ __align__(16) float g_q2p[2304];    // stage2 d2 paired [c1*9+t][pair8][2]
__device__ float g_sc[144], g_sh[144];
// offsets: s1bn0=0(16) s1bn1=16(32) s1bn2=48(32) s1bn3=80(16)
//          s2bn0=96(8) s2bn1=104(16) s2bn2=120(16) s2bn3=136(8)

typedef unsigned long long ull;

__device__ __forceinline__ void fma2(ull& d, ull a, ull b) {
    asm("fma.rn.f32x2 %0, %1, %2, %0;" : "+l"(d) : "l"(a), "l"(b));
}
__device__ __forceinline__ ull pack2(float lo, float hi) {
    ull r; asm("mov.b64 %0, {%1, %2};" : "=l"(r) : "f"(lo), "f"(hi)); return r;
}
__device__ __forceinline__ ull dup2(float v) { return pack2(v, v); }
__device__ __forceinline__ float2 unpack2(ull u) {
    float2 f; asm("mov.b64 {%0, %1}, %2;" : "=f"(f.x), "=f"(f.y) : "l"(u)); return f;
}

// padded row stride (floats) for activation tiles
#define RS 20
#define CS 320   // 16 rows * RS

// ---------------------------------------------------------------------------
// prep: reorder d2 weights, BN affine precompute, reset compaction counter
// ---------------------------------------------------------------------------
__global__ void prep_kernel(
    const float* __restrict__ s1d2w, const float* __restrict__ s2d2w,
    const float* __restrict__ b10, const float* __restrict__ b11,
    const float* __restrict__ b12, const float* __restrict__ b13,
    const float* __restrict__ b20, const float* __restrict__ b21,
    const float* __restrict__ b22, const float* __restrict__ b23)
{
    const int tid = threadIdx.x;
    if (tid == 0) g_cnt1 = 0;
    for (int i = tid; i < 9216; i += 256) {
        int c2 = i / 288, rem = i - c2 * 288;
        int c1 = rem / 9, t = rem - c1 * 9;
        g_w2p[((c1 * 9 + t) * 16 + (c2 >> 1)) * 2 + (c2 & 1)] = s1d2w[i];
    }
    for (int i = tid; i < 2304; i += 256) {
        int c2 = i / 144, rem = i - c2 * 144;
        int c1 = rem / 9, t = rem - c1 * 9;
        g_q2p[((c1 * 9 + t) * 8 + (c2 >> 1)) * 2 + (c2 & 1)] = s2d2w[i];
    }
    if (tid < 144) {
        const float* bp; int c, C;
        if      (tid < 16)  { bp = b10; c = tid;       C = 16; }
        else if (tid < 48)  { bp = b11; c = tid - 16;  C = 32; }
        else if (tid < 80)  { bp = b12; c = tid - 48;  C = 32; }
        else if (tid < 96)  { bp = b13; c = tid - 80;  C = 16; }
        else if (tid < 104) { bp = b20; c = tid - 96;  C = 8;  }
        else if (tid < 120) { bp = b21; c = tid - 104; C = 16; }
        else if (tid < 136) { bp = b22; c = tid - 120; C = 16; }
        else                { bp = b23; c = tid - 136; C = 8;  }
        float g = bp[c], b = bp[C + c], m = bp[2 * C + c], v = bp[3 * C + c];
        float s = g * rsqrtf(v + EPSV);
        g_sc[tid] = s; g_sh[tid] = b - s * m;
    }
}

// ---------------------------------------------------------------------------
// Stage 1a (all tiles): mask pool, activity vote -> compact list,
// channel conv + pool for INACTIVE tiles only.
// ---------------------------------------------------------------------------
__global__ void __launch_bounds__(256) stage1_all_kernel(
    const float* __restrict__ x, const float* __restrict__ mask,
    const float* __restrict__ cw, const float* __restrict__ cb)
{
    __shared__ float s_red[256];
    __shared__ float s_wsum[8];
    __shared__ float s_xc[16 * CS];
    __shared__ int s_active;

    const int bid = blockIdx.x;
    const int n   = bid >> 10;
    const int by  = (bid >> 5) & 31;
    const int bx  = bid & 31;
    const int tid = threadIdx.x;
    const int py  = tid >> 4, px_ = tid & 15;
    const int gy  = by * 16 + py, gx = bx * 16 + px_;

    float mval = mask[(n * 512 + gy) * 512 + gx];
    s_red[tid] = mval;
    float msum = mval;
#pragma unroll
    for (int o = 16; o; o >>= 1) msum += __shfl_xor_sync(0xffffffffu, msum, o);
    if ((tid & 31) == 0) s_wsum[tid >> 5] = msum;
    __syncthreads();

    if (tid < 64) {
        int qy = tid >> 3, qx = tid & 7;
        int p0 = (qy * 2) * 16 + qx * 2;
        float m0 = fmaxf(fmaxf(s_red[p0], s_red[p0 + 1]),
                         fmaxf(s_red[p0 + 16], s_red[p0 + 17]));
        g_mask2[(n * 256 + by * 8 + qy) * 256 + (bx * 8 + qx)] = m0;
    }
    if (tid == 0) {
        float t = 0.f;
#pragma unroll
        for (int i = 0; i < 8; i++) t += s_wsum[i];
        int act = (t > 128.0f) ? 1 : 0;
        s_active = act;
        if (act) {
            int pos = atomicAdd(&g_cnt1, 1);
            g_list1[pos] = bid;
        }
    }
    __syncthreads();
    if (s_active) return;   // active tiles handled by stage1_active_kernel

    // inactive: channel conv -> pool
    {
        const int ibase = ((n * 3) * 512 + gy) * 512 + gx;
        float xv0 = x[ibase];
        float xv1 = x[ibase + 512 * 512];
        float xv2 = x[ibase + 2 * 512 * 512];
        const int po = py * RS + px_;
#pragma unroll
        for (int c = 0; c < 16; c++) {
            float t = __ldg(&cw[c * 3 + 0]) * xv0 + __ldg(&cw[c * 3 + 1]) * xv1 +
                      __ldg(&cw[c * 3 + 2]) * xv2 + __ldg(&cb[c]);
            t = fmaxf(t, 0.0f);
            s_xc[c * CS + po] = fmaf(__ldg(&g_sc[c]), t, __ldg(&g_sh[c]));
        }
    }
    __syncthreads();

#pragma unroll
    for (int k = 0; k < 4; k++) {
        int o = tid + k * 256;
        int c = o >> 6;
        int q = o & 63;
        int qy = q >> 3, qx = q & 7;
        const float* sp = &s_xc[c * CS + (qy * 2) * RS + qx * 2];
        float mo = fmaxf(fmaxf(sp[0], sp[1]), fmaxf(sp[RS], sp[RS + 1]));
        g_x1p[((n * 16 + c) * 256 + by * 8 + qy) * 256 + (bx * 8 + qx)] = mo;
    }
}

// ---------------------------------------------------------------------------
// Stage 1b (active tiles only, compacted): channel conv + d1/d2/d3 + pool
// SMEM (floats): s_a [0..10240) padded 32xCS (d3-out flat 16x256 aliases);
//                s_b [10240..18432) compact 32x256 (s_xc padded 16xCS aliases)
// ---------------------------------------------------------------------------
__global__ void __launch_bounds__(256, 2) stage1_active_kernel(
    const float* __restrict__ x,
    const float* __restrict__ cw, const float* __restrict__ cb,
    const float* __restrict__ d1w, const float* __restrict__ d1b,
    const float* __restrict__ d2b,
    const float* __restrict__ d3w, const float* __restrict__ d3b)
{
    if ((int)blockIdx.x >= g_cnt1) return;
    const int bid = g_list1[blockIdx.x];

    extern __shared__ float sm[];
    float*  s_a   = sm;                  // padded [32][CS]
    float*  s_f   = sm;                  // d3 out flat [16][256]
    float*  s_b   = sm + 10240;          // compact [32][256]
    float*  s_xc  = s_b;                 // padded [16][CS] alias

    const int n   = bid >> 10;
    const int by  = (bid >> 5) & 31;
    const int bx  = bid & 31;
    const int tid = threadIdx.x;
    const int py  = tid >> 4, px_ = tid & 15;
    const int gy  = by * 16 + py, gx = bx * 16 + px_;

    // channel path: 1x1 conv 3->16 + bias, relu, bn  -> s_xc (padded)
    {
        const int ibase = ((n * 3) * 512 + gy) * 512 + gx;
        float xv0 = x[ibase];
        float xv1 = x[ibase + 512 * 512];
        float xv2 = x[ibase + 2 * 512 * 512];
        const int po = py * RS + px_;
#pragma unroll
        for (int c = 0; c < 16; c++) {
            float t = __ldg(&cw[c * 3 + 0]) * xv0 + __ldg(&cw[c * 3 + 1]) * xv1 +
                      __ldg(&cw[c * 3 + 2]) * xv2 + __ldg(&cb[c]);
            t = fmaxf(t, 0.0f);
            s_xc[c * CS + po] = fmaf(__ldg(&g_sc[c]), t, __ldg(&g_sh[c]));
        }
    }
    __syncthreads();

    // thread maps
    const int lane  = tid & 31;
    const int prow  = lane >> 1;          // 0..15
    const int pcol  = (lane & 1) * 8;     // 0 or 8
    const int wg    = tid >> 5;           // warp id 0..7

    // ---- d1: 1x1, 16 -> 32 ----  (8px x 4c2 per thread; pixel-pair accs)
    {
        const int c2base = wg * 4;
        ull acc[4][4];
#pragma unroll
        for (int c2 = 0; c2 < 4; c2++) {
            ull bv = dup2(__ldg(&d1b[c2base + c2]));
            acc[c2][0] = bv; acc[c2][1] = bv; acc[c2][2] = bv; acc[c2][3] = bv;
        }
        const int po = prow * RS + pcol;
#pragma unroll
        for (int c1 = 0; c1 < 16; c1++) {
            const float* p = s_xc + c1 * CS + po;
            float4 a = *(const float4*)p;
            float4 b = *(const float4*)(p + 4);
            ull va0 = pack2(a.x, a.y), va1 = pack2(a.z, a.w);
            ull vb0 = pack2(b.x, b.y), vb1 = pack2(b.z, b.w);
#pragma unroll
            for (int c2 = 0; c2 < 4; c2++) {
                ull w = dup2(__ldg(&d1w[(c2base + c2) * 16 + c1]));
                fma2(acc[c2][0], w, va0);
                fma2(acc[c2][1], w, va1);
                fma2(acc[c2][2], w, vb0);
                fma2(acc[c2][3], w, vb1);
            }
        }
#pragma unroll
        for (int c2 = 0; c2 < 4; c2++) {
            int c = c2base + c2;
            float sc = __ldg(&g_sc[16 + c]), sh = __ldg(&g_sh[16 + c]);
            float4 o0, o1;
            float2 f0 = unpack2(acc[c2][0]), f1 = unpack2(acc[c2][1]);
            float2 f2 = unpack2(acc[c2][2]), f3 = unpack2(acc[c2][3]);
            o0.x = fmaf(sc, fmaxf(f0.x, 0.f), sh); o0.y = fmaf(sc, fmaxf(f0.y, 0.f), sh);
            o0.z = fmaf(sc, fmaxf(f1.x, 0.f), sh); o0.w = fmaf(sc, fmaxf(f1.y, 0.f), sh);
            o1.x = fmaf(sc, fmaxf(f2.x, 0.f), sh); o1.y = fmaf(sc, fmaxf(f2.y, 0.f), sh);
            o1.z = fmaf(sc, fmaxf(f3.x, 0.f), sh); o1.w = fmaf(sc, fmaxf(f3.y, 0.f), sh);
            *(float4*)(s_a + (c2base + c2) * CS + po)     = o0;
            *(float4*)(s_a + (c2base + c2) * CS + po + 4) = o1;
        }
    }
    __syncthreads();

    // ---- d2: 3x3 (block-padded), 32 -> 32 ----  (8px x 4c2; channel-pair accs)
    {
        const int pairb = wg * 2;
        ull acc[2][8];
#pragma unroll
        for (int p = 0; p < 2; p++) {
            int c2 = 2 * (pairb + p);
            ull bv = pack2(__ldg(&d2b[c2]), __ldg(&d2b[c2 + 1]));
#pragma unroll
            for (int k = 0; k < 8; k++) acc[p][k] = bv;
        }
        const float* sap = s_a + pcol;
        const ulonglong2* __restrict__ wbase =
            (const ulonglong2*)g_w2p + pairb / 2;
#pragma unroll 4
        for (int c1 = 0; c1 < 32; c1++) {
            const float* cbase = sap + c1 * CS;
#pragma unroll
            for (int r = 0; r < 3; r++) {
                int yy = prow - 1 + r;
                float u0, u9; float4 m1, m2;
                if ((unsigned)yy < 16u) {
                    const float* rp = cbase + yy * RS;
                    m1 = *(const float4*)rp;
                    m2 = *(const float4*)(rp + 4);
                    u0 = pcol ? rp[-1] : 0.f;
                    u9 = pcol ? 0.f : rp[8];
                } else {
                    m1 = make_float4(0.f, 0.f, 0.f, 0.f);
                    m2 = m1; u0 = 0.f; u9 = 0.f;
                }
                ull vd[10] = {dup2(u0), dup2(m1.x), dup2(m1.y), dup2(m1.z), dup2(m1.w),
                              dup2(m2.x), dup2(m2.y), dup2(m2.z), dup2(m2.w), dup2(u9)};
                const ulonglong2* wrow = wbase + (c1 * 9 + r * 3) * 8;
#pragma unroll
                for (int dx = 0; dx < 3; dx++) {
                    ulonglong2 w = __ldg(wrow + dx * 8);
#pragma unroll
                    for (int k = 0; k < 8; k++) {
                        fma2(acc[0][k], w.x, vd[dx + k]);
                        fma2(acc[1][k], w.y, vd[dx + k]);
                    }
                }
            }
        }
        const int poc = prow * 16 + pcol;
#pragma unroll
        for (int p = 0; p < 2; p++) {
            int c2 = 2 * (pairb + p);
            float sa = __ldg(&g_sc[48 + c2]), ha = __ldg(&g_sh[48 + c2]);
            float sb2 = __ldg(&g_sc[48 + c2 + 1]), hb = __ldg(&g_sh[48 + c2 + 1]);
            float4 oa0, oa1, ob0, ob1;
            float2 f;
            f = unpack2(acc[p][0]); oa0.x = fmaf(sa, fmaxf(f.x,0.f), ha); ob0.x = fmaf(sb2, fmaxf(f.y,0.f), hb);
            f = unpack2(acc[p][1]); oa0.y = fmaf(sa, fmaxf(f.x,0.f), ha); ob0.y = fmaf(sb2, fmaxf(f.y,0.f), hb);
            f = unpack2(acc[p][2]); oa0.z = fmaf(sa, fmaxf(f.x,0.f), ha); ob0.z = fmaf(sb2, fmaxf(f.y,0.f), hb);
            f = unpack2(acc[p][3]); oa0.w = fmaf(sa, fmaxf(f.x,0.f), ha); ob0.w = fmaf(sb2, fmaxf(f.y,0.f), hb);
            f = unpack2(acc[p][4]); oa1.x = fmaf(sa, fmaxf(f.x,0.f), ha); ob1.x = fmaf(sb2, fmaxf(f.y,0.f), hb);
            f = unpack2(acc[p][5]); oa1.y = fmaf(sa, fmaxf(f.x,0.f), ha); ob1.y = fmaf(sb2, fmaxf(f.y,0.f), hb);
            f = unpack2(acc[p][6]); oa1.z = fmaf(sa, fmaxf(f.x,0.f), ha); ob1.z = fmaf(sb2, fmaxf(f.y,0.f), hb);
            f = unpack2(acc[p][7]); oa1.w = fmaf(sa, fmaxf(f.x,0.f), ha); ob1.w = fmaf(sb2, fmaxf(f.y,0.f), hb);
            *(float4*)(s_b + c2 * 256 + poc)           = oa0;
            *(float4*)(s_b + c2 * 256 + poc + 4)       = oa1;
            *(float4*)(s_b + (c2 + 1) * 256 + poc)     = ob0;
            *(float4*)(s_b + (c2 + 1) * 256 + poc + 4) = ob1;
        }
    }
    __syncthreads();

    // ---- d3: 1x1, 32 -> 16 ----  (coalesced quad map; pixel-pair accs)
    {
        const int q      = tid & 63;
        const int c2base = (tid >> 6) * 4;
        ull acc[4][2];
#pragma unroll
        for (int c2 = 0; c2 < 4; c2++) {
            ull bv = dup2(__ldg(&d3b[c2base + c2]));
            acc[c2][0] = bv; acc[c2][1] = bv;
        }
#pragma unroll 4
        for (int c1 = 0; c1 < 32; c1++) {
            float4 v = *(const float4*)(s_b + c1 * 256 + q * 4);
            ull v0 = pack2(v.x, v.y), v1 = pack2(v.z, v.w);
#pragma unroll
            for (int c2 = 0; c2 < 4; c2++) {
                ull w = dup2(__ldg(&d3w[(c2base + c2) * 32 + c1]));
                fma2(acc[c2][0], w, v0);
                fma2(acc[c2][1], w, v1);
            }
        }
#pragma unroll
        for (int c2 = 0; c2 < 4; c2++) {
            int c = c2base + c2;
            float sc = __ldg(&g_sc[80 + c]), sh = __ldg(&g_sh[80 + c]);
            float2 f0 = unpack2(acc[c2][0]), f1 = unpack2(acc[c2][1]);
            float4 o;
            o.x = fmaf(sc, fmaxf(f0.x, 0.f), sh);
            o.y = fmaf(sc, fmaxf(f0.y, 0.f), sh);
            o.z = fmaf(sc, fmaxf(f1.x, 0.f), sh);
            o.w = fmaf(sc, fmaxf(f1.y, 0.f), sh);
            *(float4*)(s_f + c * 256 + q * 4) = o;
        }
    }
    __syncthreads();

    // fused 2x2 maxpool -> g_x1p
#pragma unroll
    for (int k = 0; k < 4; k++) {
        int o = tid + k * 256;
        int c = o >> 6;
        int q = o & 63;
        int qy = q >> 3, qx = q & 7;
        const float* sp = &s_f[c * 256 + (qy * 2) * 16 + qx * 2];
        float mo = fmaxf(fmaxf(sp[0], sp[1]), fmaxf(sp[16], sp[17]));
        g_x1p[((n * 16 + c) * 256 + by * 8 + qy) * 256 + (bx * 8 + qx)] = mo;
    }
}

// ---------------------------------------------------------------------------
// Stage 2: g_x1p[16,16,256,256] -> g_x2p[16,8,128,128]
// ---------------------------------------------------------------------------
__global__ void __launch_bounds__(256, 2) stage2_kernel(
    const float* __restrict__ cw, const float* __restrict__ cb,
    const float* __restrict__ d1w, const float* __restrict__ d1b,
    const float* __restrict__ d2b,
    const float* __restrict__ d3w, const float* __restrict__ d3b)
{
    extern __shared__ float sm2[];
    float*  s_a   = sm2;
    float*  s_f   = sm2;
    float*  s_b   = sm2 + 5120;
    float*  s_xc  = s_b;

    __shared__ float s_wsum[8];
    __shared__ int s_active;

    const int bid = blockIdx.x;
    const int n   = bid >> 8;
    const int by  = (bid >> 4) & 15;
    const int bx  = bid & 15;
    const int tid = threadIdx.x;
    const int py  = tid >> 4, px_ = tid & 15;
    const int gy  = by * 16 + py, gx = bx * 16 + px_;

    {
        float mv = g_mask2[(n * 256 + gy) * 256 + gx];
#pragma unroll
        for (int o = 16; o; o >>= 1) mv += __shfl_xor_sync(0xffffffffu, mv, o);
        if ((tid & 31) == 0) s_wsum[tid >> 5] = mv;
    }
    __syncthreads();
    if (tid == 0) {
        float t = 0.f;
#pragma unroll
        for (int i = 0; i < 8; i++) t += s_wsum[i];
        s_active = (t > 128.0f) ? 1 : 0;
    }

    // channel path: 1x1 conv 16->8 -> s_xc (padded)
    {
        const int ibase = ((n * 16) * 256 + gy) * 256 + gx;
        float xin[16];
#pragma unroll
        for (int c = 0; c < 16; c++) xin[c] = g_x1p[ibase + c * 65536];
        const int po = py * RS + px_;
#pragma unroll
        for (int c2 = 0; c2 < 8; c2++) {
            float t = __ldg(&cb[c2]);
#pragma unroll
            for (int c1 = 0; c1 < 16; c1++)
                t = fmaf(xin[c1], __ldg(&cw[c2 * 16 + c1]), t);
            t = fmaxf(t, 0.0f);
            s_xc[c2 * CS + po] = fmaf(__ldg(&g_sc[96 + c2]), t, __ldg(&g_sh[96 + c2]));
        }
    }
    __syncthreads();

    const int act  = s_active;
    const int lane = tid & 31;
    const int wg   = tid >> 5;

    if (act) {
        // ---- d1: 1x1, 8 -> 16 ----
        {
            const int prow = lane >> 1;
            const int pcol = (lane & 1) * 8;
            const int c2base = wg * 2;
            const int po = prow * RS + pcol;
            ull acc[2][4];
#pragma unroll
            for (int c2 = 0; c2 < 2; c2++) {
                ull bv = dup2(__ldg(&d1b[c2base + c2]));
                acc[c2][0] = bv; acc[c2][1] = bv; acc[c2][2] = bv; acc[c2][3] = bv;
            }
#pragma unroll
            for (int c1 = 0; c1 < 8; c1++) {
                const float* p = s_xc + c1 * CS + po;
                float4 a = *(const float4*)p;
                float4 b = *(const float4*)(p + 4);
                ull va0 = pack2(a.x, a.y), va1 = pack2(a.z, a.w);
                ull vb0 = pack2(b.x, b.y), vb1 = pack2(b.z, b.w);
#pragma unroll
                for (int c2 = 0; c2 < 2; c2++) {
                    ull w = dup2(__ldg(&d1w[(c2base + c2) * 8 + c1]));
                    fma2(acc[c2][0], w, va0);
                    fma2(acc[c2][1], w, va1);
                    fma2(acc[c2][2], w, vb0);
                    fma2(acc[c2][3], w, vb1);
                }
            }
#pragma unroll
            for (int c2 = 0; c2 < 2; c2++) {
                int c = c2base + c2;
                float sc = __ldg(&g_sc[104 + c]), sh = __ldg(&g_sh[104 + c]);
                float2 f0 = unpack2(acc[c2][0]), f1 = unpack2(acc[c2][1]);
                float2 f2 = unpack2(acc[c2][2]), f3 = unpack2(acc[c2][3]);
                float4 o0, o1;
                o0.x = fmaf(sc, fmaxf(f0.x, 0.f), sh); o0.y = fmaf(sc, fmaxf(f0.y, 0.f), sh);
                o0.z = fmaf(sc, fmaxf(f1.x, 0.f), sh); o0.w = fmaf(sc, fmaxf(f1.y, 0.f), sh);
                o1.x = fmaf(sc, fmaxf(f2.x, 0.f), sh); o1.y = fmaf(sc, fmaxf(f2.y, 0.f), sh);
                o1.z = fmaf(sc, fmaxf(f3.x, 0.f), sh); o1.w = fmaf(sc, fmaxf(f3.y, 0.f), sh);
                *(float4*)(s_a + c * CS + po)     = o0;
                *(float4*)(s_a + c * CS + po + 4) = o1;
            }
        }
        __syncthreads();

        // ---- d2: 3x3, 16 -> 16 ----
        {
            const int pg    = tid & 63;
            const int prow4 = pg >> 2;
            const int pcol4 = (pg & 3) * 4;
            const int pairb = (tid >> 6) * 2;
            ull acc[2][4];
#pragma unroll
            for (int p = 0; p < 2; p++) {
                int c2 = 2 * (pairb + p);
                ull bv = pack2(__ldg(&d2b[c2]), __ldg(&d2b[c2 + 1]));
                acc[p][0] = bv; acc[p][1] = bv; acc[p][2] = bv; acc[p][3] = bv;
            }
            const float* sap = s_a + pcol4;
            const ulonglong2* __restrict__ wbase =
                (const ulonglong2*)g_q2p + pairb / 2;
#pragma unroll 4
            for (int c1 = 0; c1 < 16; c1++) {
                const float* cbase = sap + c1 * CS;
#pragma unroll
                for (int r = 0; r < 3; r++) {
                    int yy = prow4 - 1 + r;
                    float v0, v5; float4 m;
                    if ((unsigned)yy < 16u) {
                        const float* rp = cbase + yy * RS;
                        m = *(const float4*)rp;
                        v0 = (pcol4 > 0)  ? rp[-1] : 0.f;
                        v5 = (pcol4 < 12) ? rp[4]  : 0.f;
                    } else { m = make_float4(0.f,0.f,0.f,0.f); v0 = 0.f; v5 = 0.f; }
                    ull vd[6] = {dup2(v0), dup2(m.x), dup2(m.y), dup2(m.z), dup2(m.w), dup2(v5)};
                    const ulonglong2* wrow = wbase + (c1 * 9 + r * 3) * 4;
#pragma unroll
                    for (int dx = 0; dx < 3; dx++) {
                        ulonglong2 w = __ldg(wrow + dx * 4);
#pragma unroll
                        for (int k = 0; k < 4; k++) {
                            fma2(acc[0][k], w.x, vd[dx + k]);
                            fma2(acc[1][k], w.y, vd[dx + k]);
                        }
                    }
                }
            }
            const int poc = prow4 * 16 + pcol4;
#pragma unroll
            for (int p = 0; p < 2; p++) {
                int c2 = 2 * (pairb + p);
                float sa = __ldg(&g_sc[120 + c2]), ha = __ldg(&g_sh[120 + c2]);
                float sb2 = __ldg(&g_sc[120 + c2 + 1]), hb = __ldg(&g_sh[120 + c2 + 1]);
                float4 oa, ob;
                float2 f;
                f = unpack2(acc[p][0]); oa.x = fmaf(sa, fmaxf(f.x,0.f), ha); ob.x = fmaf(sb2, fmaxf(f.y,0.f), hb);
                f = unpack2(acc[p][1]); oa.y = fmaf(sa, fmaxf(f.x,0.f), ha); ob.y = fmaf(sb2, fmaxf(f.y,0.f), hb);
                f = unpack2(acc[p][2]); oa.z = fmaf(sa, fmaxf(f.x,0.f), ha); ob.z = fmaf(sb2, fmaxf(f.y,0.f), hb);
                f = unpack2(acc[p][3]); oa.w = fmaf(sa, fmaxf(f.x,0.f), ha); ob.w = fmaf(sb2, fmaxf(f.y,0.f), hb);
                *(float4*)(s_b + c2 * 256 + poc)       = oa;
                *(float4*)(s_b + (c2 + 1) * 256 + poc) = ob;
            }
        }
        __syncthreads();

        // ---- d3: 1x1, 16 -> 8 ----
        {
            const int q      = tid & 63;
            const int c2base = (tid >> 6) * 2;
            ull acc[2][2];
#pragma unroll
            for (int c2 = 0; c2 < 2; c2++) {
                ull bv = dup2(__ldg(&d3b[c2base + c2]));
                acc[c2][0] = bv; acc[c2][1] = bv;
            }
#pragma unroll
            for (int c1 = 0; c1 < 16; c1++) {
                float4 v = *(const float4*)(s_b + c1 * 256 + q * 4);
                ull v0 = pack2(v.x, v.y), v1 = pack2(v.z, v.w);
#pragma unroll
                for (int c2 = 0; c2 < 2; c2++) {
                    ull w = dup2(__ldg(&d3w[(c2base + c2) * 16 + c1]));
                    fma2(acc[c2][0], w, v0);
                    fma2(acc[c2][1], w, v1);
                }
            }
#pragma unroll
            for (int c2 = 0; c2 < 2; c2++) {
                int c = c2base + c2;
                float sc = __ldg(&g_sc[136 + c]), sh = __ldg(&g_sh[136 + c]);
                float2 f0 = unpack2(acc[c2][0]), f1 = unpack2(acc[c2][1]);
                float4 o;
                o.x = fmaf(sc, fmaxf(f0.x, 0.f), sh);
                o.y = fmaf(sc, fmaxf(f0.y, 0.f), sh);
                o.z = fmaf(sc, fmaxf(f1.x, 0.f), sh);
                o.w = fmaf(sc, fmaxf(f1.y, 0.f), sh);
                *(float4*)(s_f + c * 256 + q * 4) = o;
            }
        }
        __syncthreads();
    }

    // fused maxpool -> g_x2p
    const float* srcp = act ? s_f : s_xc;
    const int chs = act ? 256 : CS;
    const int rs  = act ? 16 : RS;
#pragma unroll
    for (int k = 0; k < 2; k++) {
        int o = tid + k * 256;
        int c = o >> 6;
        int q = o & 63;
        int qy = q >> 3, qx = q & 7;
        const float* sp = &srcp[c * chs + (qy * 2) * rs + qx * 2];
        float mo = fmaxf(fmaxf(sp[0], sp[1]), fmaxf(sp[rs], sp[rs + 1]));
        g_x2p[((n * 8 + c) * 128 + by * 8 + qy) * 128 + (bx * 8 + qx)] = mo;
    }
}

// ---------------------------------------------------------------------------
// FC (split-K x32, vectorized) + softmax
// ---------------------------------------------------------------------------
__global__ void __launch_bounds__(256) fc_partial_kernel(const float* __restrict__ fc_w)
{
    const int b = blockIdx.x;       // 0..511
    const int n = b >> 5, s = b & 31;
    const int tid = threadIdx.x;
    const float4* f = (const float4*)(g_x2p + n * 131072 + s * 4096);
    const float4* w = (const float4*)(fc_w) + s * 1024;

    float part[10];
#pragma unroll
    for (int k = 0; k < 10; k++) part[k] = 0.0f;

#pragma unroll
    for (int j = tid; j < 1024; j += 256) {
        float4 fv = f[j];
#pragma unroll
        for (int k = 0; k < 10; k++) {
            float4 wv = __ldg(&w[k * 32768 + j]);
            part[k] += fv.x * wv.x + fv.y * wv.y + fv.z * wv.z + fv.w * wv.w;
        }
    }

    __shared__ float sred[10][256];
#pragma unroll
    for (int k = 0; k < 10; k++) sred[k][tid] = part[k];
    __syncthreads();
    for (int st = 128; st > 0; st >>= 1) {
        if (tid < st) {
#pragma unroll
            for (int k = 0; k < 10; k++) sred[k][tid] += sred[k][tid + st];
        }
        __syncthreads();
    }
    if (tid < 10) g_fcpart[(n * 32 + s) * 10 + tid] = sred[tid][0];
}

__global__ void fc_final_kernel(const float* __restrict__ fc_b, float* __restrict__ out)
{
    const int t = threadIdx.x;
    __shared__ float s_l[16][10];
    if (t < 160) {
        int n = t / 10, k = t - n * 10;
        float a = fc_b[k];
#pragma unroll
        for (int s = 0; s < 32; s++) a += g_fcpart[(n * 32 + s) * 10 + k];
        s_l[n][k] = a;
    }
    __syncthreads();
    if (t < 16) {
        float mx = -1e30f;
#pragma unroll
        for (int k = 0; k < 10; k++) mx = fmaxf(mx, s_l[t][k]);
        float e[10], se = 0.f;
#pragma unroll
        for (int k = 0; k < 10; k++) { e[k] = expf(s_l[t][k] - mx); se += e[k]; }
        float inv = 1.0f / se;
#pragma unroll
        for (int k = 0; k < 10; k++) out[t * 10 + k] = e[k] * inv;
    }
}

// ---------------------------------------------------------------------------
extern "C" void kernel_launch(void* const* d_in, const int* in_sizes, int n_in,
                              void* d_out, int out_size)
{
    const float* x      = (const float*)d_in[0];
    const float* mask   = (const float*)d_in[1];
    const float* s1_cw  = (const float*)d_in[2];
    const float* s1_cb  = (const float*)d_in[3];
    const float* s1_bn0 = (const float*)d_in[4];
    const float* s1_d1w = (const float*)d_in[5];
    const float* s1_d1b = (const float*)d_in[6];
    const float* s1_bn1 = (const float*)d_in[7];
    const float* s1_d2w = (const float*)d_in[8];
    const float* s1_d2b = (const float*)d_in[9];
    const float* s1_bn2 = (const float*)d_in[10];
    const float* s1_d3w = (const float*)d_in[11];
    const float* s1_d3b = (const float*)d_in[12];
    const float* s1_bn3 = (const float*)d_in[13];
    const float* s2_cw  = (const float*)d_in[14];
    const float* s2_cb  = (const float*)d_in[15];
    const float* s2_bn0 = (const float*)d_in[16];
    const float* s2_d1w = (const float*)d_in[17];
    const float* s2_d1b = (const float*)d_in[18];
    const float* s2_bn1 = (const float*)d_in[19];
    const float* s2_d2w = (const float*)d_in[20];
    const float* s2_d2b = (const float*)d_in[21];
    const float* s2_bn2 = (const float*)d_in[22];
    const float* s2_d3w = (const float*)d_in[23];
    const float* s2_d3b = (const float*)d_in[24];
    const float* s2_bn3 = (const float*)d_in[25];
    const float* fc_w   = (const float*)d_in[26];
    const float* fc_b   = (const float*)d_in[27];

    prep_kernel<<<1, 256>>>(s1_d2w, s2_d2w,
                            s1_bn0, s1_bn1, s1_bn2, s1_bn3,
                            s2_bn0, s2_bn1, s2_bn2, s2_bn3);

    stage1_all_kernel<<<16 * 32 * 32, 256>>>(x, mask, s1_cw, s1_cb);

    const int smem1 = 18432 * sizeof(float);   // 72 KB dynamic
    cudaFuncSetAttribute(stage1_active_kernel, cudaFuncAttributeMaxDynamicSharedMemorySize, smem1);
    stage1_active_kernel<<<16 * 32 * 32, 256, smem1>>>(
        x, s1_cw, s1_cb, s1_d1w, s1_d1b, s1_d2b, s1_d3w, s1_d3b);

    const int smem2 = 9216 * sizeof(float);    // 36 KB dynamic
    cudaFuncSetAttribute(stage2_kernel, cudaFuncAttributeMaxDynamicSharedMemorySize, smem2);
    stage2_kernel<<<16 * 16 * 16, 256, smem2>>>(
        s2_cw, s2_cb, s2_d1w, s2_d1b, s2_d2b, s2_d3w, s2_d3b);

    fc_partial_kernel<<<512, 256>>>(fc_w);
    fc_final_kernel<<<1, 256>>>(fc_b, (float*)d_out);
}

// round 6
// speedup vs baseline: 1.5333x; 1.1461x over previous
#include <cuda_runtime.h>

#define EPSV 1e-5f

// scratch (no cudaMalloc allowed)
__device__ float g_x1p[16 * 16 * 256 * 256];   // stage1 output, pooled  [N,16,256,256]
__device__ float g_mask2[16 * 256 * 256];      // pooled mask            [N,256,256]
__device__ float g_x2p[16 * 8 * 128 * 128];    // stage2 output, pooled  [N,8,128,128]
__device__ float g_fcpart[16 * 32 * 10];       // FC partial sums
__device__ int   g_cnt1;                       // active tile count (stage1)
__device__ int   g_list1[16384];               // active tile list  (stage1)

// prepped weights / BN (global; read warp-uniform via L1)
__device__ __align__(16) float g_w2p[9216];    // stage1 d2 paired [c1*9+t][pair16][2]
__device__ __align__(16) float g_q2p[2304];    // stage2 d2 paired [c1*9+t][pair8][2]
__device__ float g_sc[144], g_sh[144];
// offsets: s1bn0=0(16) s1bn1=16(32) s1bn2=48(32) s1bn3=80(16)
//          s2bn0=96(8) s2bn1=104(16) s2bn2=120(16) s2bn3=136(8)

typedef unsigned long long ull;

__device__ __forceinline__ void fma2(ull& d, ull a, ull b) {
    asm("fma.rn.f32x2 %0, %1, %2, %0;" : "+l"(d) : "l"(a), "l"(b));
}
__device__ __forceinline__ ull pack2(float lo, float hi) {
    ull r; asm("mov.b64 %0, {%1, %2};" : "=l"(r) : "f"(lo), "f"(hi)); return r;
}
__device__ __forceinline__ ull dup2(float v) { return pack2(v, v); }
__device__ __forceinline__ float2 unpack2(ull u) {
    float2 f; asm("mov.b64 {%0, %1}, %2;" : "=f"(f.x), "=f"(f.y) : "l"(u)); return f;
}

// padded row stride (floats) for activation tiles
#define RS 20
#define CS 320   // 16 rows * RS

// ---------------------------------------------------------------------------
// prep: reorder d2 weights, BN affine precompute, reset compaction counter
// ---------------------------------------------------------------------------
__global__ void prep_kernel(
    const float* __restrict__ s1d2w, const float* __restrict__ s2d2w,
    const float* __restrict__ b10, const float* __restrict__ b11,
    const float* __restrict__ b12, const float* __restrict__ b13,
    const float* __restrict__ b20, const float* __restrict__ b21,
    const float* __restrict__ b22, const float* __restrict__ b23)
{
    const int tid = threadIdx.x;
    if (tid == 0) g_cnt1 = 0;
    for (int i = tid; i < 9216; i += 256) {
        int c2 = i / 288, rem = i - c2 * 288;
        int c1 = rem / 9, t = rem - c1 * 9;
        g_w2p[((c1 * 9 + t) * 16 + (c2 >> 1)) * 2 + (c2 & 1)] = s1d2w[i];
    }
    for (int i = tid; i < 2304; i += 256) {
        int c2 = i / 144, rem = i - c2 * 144;
        int c1 = rem / 9, t = rem - c1 * 9;
        g_q2p[((c1 * 9 + t) * 8 + (c2 >> 1)) * 2 + (c2 & 1)] = s2d2w[i];
    }
    if (tid < 144) {
        const float* bp; int c, C;
        if      (tid < 16)  { bp = b10; c = tid;       C = 16; }
        else if (tid < 48)  { bp = b11; c = tid - 16;  C = 32; }
        else if (tid < 80)  { bp = b12; c = tid - 48;  C = 32; }
        else if (tid < 96)  { bp = b13; c = tid - 80;  C = 16; }
        else if (tid < 104) { bp = b20; c = tid - 96;  C = 8;  }
        else if (tid < 120) { bp = b21; c = tid - 104; C = 16; }
        else if (tid < 136) { bp = b22; c = tid - 120; C = 16; }
        else                { bp = b23; c = tid - 136; C = 8;  }
        float g = bp[c], b = bp[C + c], m = bp[2 * C + c], v = bp[3 * C + c];
        float s = g * rsqrtf(v + EPSV);
        g_sc[tid] = s; g_sh[tid] = b - s * m;
    }
}

// ---------------------------------------------------------------------------
// Stage 1a (all tiles): mask pool, activity vote -> compact list,
// channel conv + pool for INACTIVE tiles only.
// ---------------------------------------------------------------------------
__global__ void __launch_bounds__(256) stage1_all_kernel(
    const float* __restrict__ x, const float* __restrict__ mask,
    const float* __restrict__ cw, const float* __restrict__ cb)
{
    __shared__ float s_red[256];
    __shared__ float s_wsum[8];
    __shared__ float s_xc[16 * CS];
    __shared__ int s_active;

    const int bid = blockIdx.x;
    const int n   = bid >> 10;
    const int by  = (bid >> 5) & 31;
    const int bx  = bid & 31;
    const int tid = threadIdx.x;
    const int py  = tid >> 4, px_ = tid & 15;
    const int gy  = by * 16 + py, gx = bx * 16 + px_;

    float mval = mask[(n * 512 + gy) * 512 + gx];
    s_red[tid] = mval;
    float msum = mval;
#pragma unroll
    for (int o = 16; o; o >>= 1) msum += __shfl_xor_sync(0xffffffffu, msum, o);
    if ((tid & 31) == 0) s_wsum[tid >> 5] = msum;
    __syncthreads();

    if (tid < 64) {
        int qy = tid >> 3, qx = tid & 7;
        int p0 = (qy * 2) * 16 + qx * 2;
        float m0 = fmaxf(fmaxf(s_red[p0], s_red[p0 + 1]),
                         fmaxf(s_red[p0 + 16], s_red[p0 + 17]));
        g_mask2[(n * 256 + by * 8 + qy) * 256 + (bx * 8 + qx)] = m0;
    }
    if (tid == 0) {
        float t = 0.f;
#pragma unroll
        for (int i = 0; i < 8; i++) t += s_wsum[i];
        int act = (t > 128.0f) ? 1 : 0;
        s_active = act;
        if (act) {
            int pos = atomicAdd(&g_cnt1, 1);
            g_list1[pos] = bid;
        }
    }
    __syncthreads();
    if (s_active) return;   // active tiles handled by stage1_active_kernel

    // inactive: channel conv -> pool
    {
        const int ibase = ((n * 3) * 512 + gy) * 512 + gx;
        float xv0 = x[ibase];
        float xv1 = x[ibase + 512 * 512];
        float xv2 = x[ibase + 2 * 512 * 512];
        const int po = py * RS + px_;
#pragma unroll
        for (int c = 0; c < 16; c++) {
            float t = __ldg(&cw[c * 3 + 0]) * xv0 + __ldg(&cw[c * 3 + 1]) * xv1 +
                      __ldg(&cw[c * 3 + 2]) * xv2 + __ldg(&cb[c]);
            t = fmaxf(t, 0.0f);
            s_xc[c * CS + po] = fmaf(__ldg(&g_sc[c]), t, __ldg(&g_sh[c]));
        }
    }
    __syncthreads();

#pragma unroll
    for (int k = 0; k < 4; k++) {
        int o = tid + k * 256;
        int c = o >> 6;
        int q = o & 63;
        int qy = q >> 3, qx = q & 7;
        const float* sp = &s_xc[c * CS + (qy * 2) * RS + qx * 2];
        float mo = fmaxf(fmaxf(sp[0], sp[1]), fmaxf(sp[RS], sp[RS + 1]));
        g_x1p[((n * 16 + c) * 256 + by * 8 + qy) * 256 + (bx * 8 + qx)] = mo;
    }
}

// ---------------------------------------------------------------------------
// Stage 1b (active tiles only, compacted): channel conv + d1/d2/d3 + pool
// Lane map (conflict-free LDS): prow = lane&15, pcol = (lane>>4)*8.
// SMEM (floats): s_a [0..10240) padded 32xCS (d3-out flat 16x256 aliases);
//                s_b [10240..18432) compact 32x256 (s_xc padded 16xCS aliases)
// ---------------------------------------------------------------------------
__global__ void __launch_bounds__(256, 2) stage1_active_kernel(
    const float* __restrict__ x,
    const float* __restrict__ cw, const float* __restrict__ cb,
    const float* __restrict__ d1w, const float* __restrict__ d1b,
    const float* __restrict__ d2b,
    const float* __restrict__ d3w, const float* __restrict__ d3b)
{
    if ((int)blockIdx.x >= g_cnt1) return;
    const int bid = g_list1[blockIdx.x];

    extern __shared__ float sm[];
    float*  s_a   = sm;                  // padded [32][CS]
    float*  s_f   = sm;                  // d3 out flat [16][256]
    float*  s_b   = sm + 10240;          // compact [32][256]
    float*  s_xc  = s_b;                 // padded [16][CS] alias

    const int n   = bid >> 10;
    const int by  = (bid >> 5) & 31;
    const int bx  = bid & 31;
    const int tid = threadIdx.x;
    const int py  = tid >> 4, px_ = tid & 15;
    const int gy  = by * 16 + py, gx = bx * 16 + px_;

    // channel path: 1x1 conv 3->16 + bias, relu, bn  -> s_xc (padded)
    {
        const int ibase = ((n * 3) * 512 + gy) * 512 + gx;
        float xv0 = x[ibase];
        float xv1 = x[ibase + 512 * 512];
        float xv2 = x[ibase + 2 * 512 * 512];
        const int po = py * RS + px_;
#pragma unroll
        for (int c = 0; c < 16; c++) {
            float t = __ldg(&cw[c * 3 + 0]) * xv0 + __ldg(&cw[c * 3 + 1]) * xv1 +
                      __ldg(&cw[c * 3 + 2]) * xv2 + __ldg(&cb[c]);
            t = fmaxf(t, 0.0f);
            s_xc[c * CS + po] = fmaf(__ldg(&g_sc[c]), t, __ldg(&g_sh[c]));
        }
    }
    __syncthreads();

    // conflict-free lane map: 8 distinct rows per LDS phase
    const int lane  = tid & 31;
    const int prow  = lane & 15;          // 0..15
    const int pcol  = (lane >> 4) * 8;    // 0 or 8
    const int wg    = tid >> 5;           // warp id 0..7

    // ---- d1: 1x1, 16 -> 32 ----  (8px x 4c2 per thread; pixel-pair accs)
    {
        const int c2base = wg * 4;
        ull acc[4][4];
#pragma unroll
        for (int c2 = 0; c2 < 4; c2++) {
            ull bv = dup2(__ldg(&d1b[c2base + c2]));
            acc[c2][0] = bv; acc[c2][1] = bv; acc[c2][2] = bv; acc[c2][3] = bv;
        }
        const int po = prow * RS + pcol;
#pragma unroll
        for (int c1 = 0; c1 < 16; c1++) {
            const float* p = s_xc + c1 * CS + po;
            float4 a = *(const float4*)p;
            float4 b = *(const float4*)(p + 4);
            ull va0 = pack2(a.x, a.y), va1 = pack2(a.z, a.w);
            ull vb0 = pack2(b.x, b.y), vb1 = pack2(b.z, b.w);
#pragma unroll
            for (int c2 = 0; c2 < 4; c2++) {
                ull w = dup2(__ldg(&d1w[(c2base + c2) * 16 + c1]));
                fma2(acc[c2][0], w, va0);
                fma2(acc[c2][1], w, va1);
                fma2(acc[c2][2], w, vb0);
                fma2(acc[c2][3], w, vb1);
            }
        }
#pragma unroll
        for (int c2 = 0; c2 < 4; c2++) {
            int c = c2base + c2;
            float sc = __ldg(&g_sc[16 + c]), sh = __ldg(&g_sh[16 + c]);
            float4 o0, o1;
            float2 f0 = unpack2(acc[c2][0]), f1 = unpack2(acc[c2][1]);
            float2 f2 = unpack2(acc[c2][2]), f3 = unpack2(acc[c2][3]);
            o0.x = fmaf(sc, fmaxf(f0.x, 0.f), sh); o0.y = fmaf(sc, fmaxf(f0.y, 0.f), sh);
            o0.z = fmaf(sc, fmaxf(f1.x, 0.f), sh); o0.w = fmaf(sc, fmaxf(f1.y, 0.f), sh);
            o1.x = fmaf(sc, fmaxf(f2.x, 0.f), sh); o1.y = fmaf(sc, fmaxf(f2.y, 0.f), sh);
            o1.z = fmaf(sc, fmaxf(f3.x, 0.f), sh); o1.w = fmaf(sc, fmaxf(f3.y, 0.f), sh);
            *(float4*)(s_a + c * CS + po)     = o0;
            *(float4*)(s_a + c * CS + po + 4) = o1;
        }
    }
    __syncthreads();

    // ---- d2: 3x3 (block-padded), 32 -> 32 ----  (8px x 4c2; channel-pair accs)
    {
        const int pairb = wg * 2;
        ull acc[2][8];
#pragma unroll
        for (int p = 0; p < 2; p++) {
            int c2 = 2 * (pairb + p);
            ull bv = pack2(__ldg(&d2b[c2]), __ldg(&d2b[c2 + 1]));
#pragma unroll
            for (int k = 0; k < 8; k++) acc[p][k] = bv;
        }
        const float* sap = s_a + pcol;
        const ulonglong2* __restrict__ wbase =
            (const ulonglong2*)g_w2p + pairb / 2;
#pragma unroll 4
        for (int c1 = 0; c1 < 32; c1++) {
            const float* cbase = sap + c1 * CS;
#pragma unroll
            for (int r = 0; r < 3; r++) {
                int yy = prow - 1 + r;
                float u0, u9; float4 m1, m2;
                if ((unsigned)yy < 16u) {
                    const float* rp = cbase + yy * RS;
                    m1 = *(const float4*)rp;
                    m2 = *(const float4*)(rp + 4);
                    u0 = pcol ? rp[-1] : 0.f;
                    u9 = pcol ? 0.f : rp[8];
                } else {
                    m1 = make_float4(0.f, 0.f, 0.f, 0.f);
                    m2 = m1; u0 = 0.f; u9 = 0.f;
                }
                ull vd[10] = {dup2(u0), dup2(m1.x), dup2(m1.y), dup2(m1.z), dup2(m1.w),
                              dup2(m2.x), dup2(m2.y), dup2(m2.z), dup2(m2.w), dup2(u9)};
                const ulonglong2* wrow = wbase + (c1 * 9 + r * 3) * 8;
#pragma unroll
                for (int dx = 0; dx < 3; dx++) {
                    ulonglong2 w = __ldg(wrow + dx * 8);
#pragma unroll
                    for (int k = 0; k < 8; k++) {
                        fma2(acc[0][k], w.x, vd[dx + k]);
                        fma2(acc[1][k], w.y, vd[dx + k]);
                    }
                }
            }
        }
        const int poc = prow * 16 + pcol;
#pragma unroll
        for (int p = 0; p < 2; p++) {
            int c2 = 2 * (pairb + p);
            float sa = __ldg(&g_sc[48 + c2]), ha = __ldg(&g_sh[48 + c2]);
            float sb2 = __ldg(&g_sc[48 + c2 + 1]), hb = __ldg(&g_sh[48 + c2 + 1]);
            float4 oa0, oa1, ob0, ob1;
            float2 f;
            f = unpack2(acc[p][0]); oa0.x = fmaf(sa, fmaxf(f.x,0.f), ha); ob0.x = fmaf(sb2, fmaxf(f.y,0.f), hb);
            f = unpack2(acc[p][1]); oa0.y = fmaf(sa, fmaxf(f.x,0.f), ha); ob0.y = fmaf(sb2, fmaxf(f.y,0.f), hb);
            f = unpack2(acc[p][2]); oa0.z = fmaf(sa, fmaxf(f.x,0.f), ha); ob0.z = fmaf(sb2, fmaxf(f.y,0.f), hb);
            f = unpack2(acc[p][3]); oa0.w = fmaf(sa, fmaxf(f.x,0.f), ha); ob0.w = fmaf(sb2, fmaxf(f.y,0.f), hb);
            f = unpack2(acc[p][4]); oa1.x = fmaf(sa, fmaxf(f.x,0.f), ha); ob1.x = fmaf(sb2, fmaxf(f.y,0.f), hb);
            f = unpack2(acc[p][5]); oa1.y = fmaf(sa, fmaxf(f.x,0.f), ha); ob1.y = fmaf(sb2, fmaxf(f.y,0.f), hb);
            f = unpack2(acc[p][6]); oa1.z = fmaf(sa, fmaxf(f.x,0.f), ha); ob1.z = fmaf(sb2, fmaxf(f.y,0.f), hb);
            f = unpack2(acc[p][7]); oa1.w = fmaf(sa, fmaxf(f.x,0.f), ha); ob1.w = fmaf(sb2, fmaxf(f.y,0.f), hb);
            *(float4*)(s_b + c2 * 256 + poc)           = oa0;
            *(float4*)(s_b + c2 * 256 + poc + 4)       = oa1;
            *(float4*)(s_b + (c2 + 1) * 256 + poc)     = ob0;
            *(float4*)(s_b + (c2 + 1) * 256 + poc + 4) = ob1;
        }
    }
    __syncthreads();

    // ---- d3: 1x1, 32 -> 16 ----  (coalesced quad map; pixel-pair accs)
    {
        const int q      = tid & 63;
        const int c2base = (tid >> 6) * 4;
        ull acc[4][2];
#pragma unroll
        for (int c2 = 0; c2 < 4; c2++) {
            ull bv = dup2(__ldg(&d3b[c2base + c2]));
            acc[c2][0] = bv; acc[c2][1] = bv;
        }
#pragma unroll 4
        for (int c1 = 0; c1 < 32; c1++) {
            float4 v = *(const float4*)(s_b + c1 * 256 + q * 4);
            ull v0 = pack2(v.x, v.y), v1 = pack2(v.z, v.w);
#pragma unroll
            for (int c2 = 0; c2 < 4; c2++) {
                ull w = dup2(__ldg(&d3w[(c2base + c2) * 32 + c1]));
                fma2(acc[c2][0], w, v0);
                fma2(acc[c2][1], w, v1);
            }
        }
#pragma unroll
        for (int c2 = 0; c2 < 4; c2++) {
            int c = c2base + c2;
            float sc = __ldg(&g_sc[80 + c]), sh = __ldg(&g_sh[80 + c]);
            float2 f0 = unpack2(acc[c2][0]), f1 = unpack2(acc[c2][1]);
            float4 o;
            o.x = fmaf(sc, fmaxf(f0.x, 0.f), sh);
            o.y = fmaf(sc, fmaxf(f0.y, 0.f), sh);
            o.z = fmaf(sc, fmaxf(f1.x, 0.f), sh);
            o.w = fmaf(sc, fmaxf(f1.y, 0.f), sh);
            *(float4*)(s_f + c * 256 + q * 4) = o;
        }
    }
    __syncthreads();

    // fused 2x2 maxpool -> g_x1p
#pragma unroll
    for (int k = 0; k < 4; k++) {
        int o = tid + k * 256;
        int c = o >> 6;
        int q = o & 63;
        int qy = q >> 3, qx = q & 7;
        const float* sp = &s_f[c * 256 + (qy * 2) * 16 + qx * 2];
        float mo = fmaxf(fmaxf(sp[0], sp[1]), fmaxf(sp[16], sp[17]));
        g_x1p[((n * 16 + c) * 256 + by * 8 + qy) * 256 + (bx * 8 + qx)] = mo;
    }
}

// ---------------------------------------------------------------------------
// Stage 2: g_x1p[16,16,256,256] -> g_x2p[16,8,128,128]
// d2 remapped to 8px x 2c2 (one c2-pair per warp), conflict-free lane map,
// occupancy target 3 CTAs/SM.
// ---------------------------------------------------------------------------
__global__ void __launch_bounds__(256, 3) stage2_kernel(
    const float* __restrict__ cw, const float* __restrict__ cb,
    const float* __restrict__ d1w, const float* __restrict__ d1b,
    const float* __restrict__ d2b,
    const float* __restrict__ d3w, const float* __restrict__ d3b)
{
    extern __shared__ float sm2[];
    float*  s_a   = sm2;
    float*  s_f   = sm2;
    float*  s_b   = sm2 + 5120;
    float*  s_xc  = s_b;

    __shared__ float s_wsum[8];
    __shared__ int s_active;

    const int bid = blockIdx.x;
    const int n   = bid >> 8;
    const int by  = (bid >> 4) & 15;
    const int bx  = bid & 15;
    const int tid = threadIdx.x;
    const int py  = tid >> 4, px_ = tid & 15;
    const int gy  = by * 16 + py, gx = bx * 16 + px_;

    {
        float mv = g_mask2[(n * 256 + gy) * 256 + gx];
#pragma unroll
        for (int o = 16; o; o >>= 1) mv += __shfl_xor_sync(0xffffffffu, mv, o);
        if ((tid & 31) == 0) s_wsum[tid >> 5] = mv;
    }
    __syncthreads();
    if (tid == 0) {
        float t = 0.f;
#pragma unroll
        for (int i = 0; i < 8; i++) t += s_wsum[i];
        s_active = (t > 128.0f) ? 1 : 0;
    }

    // channel path: 1x1 conv 16->8 -> s_xc (padded)
    {
        const int ibase = ((n * 16) * 256 + gy) * 256 + gx;
        float xin[16];
#pragma unroll
        for (int c = 0; c < 16; c++) xin[c] = g_x1p[ibase + c * 65536];
        const int po = py * RS + px_;
#pragma unroll
        for (int c2 = 0; c2 < 8; c2++) {
            float t = __ldg(&cb[c2]);
#pragma unroll
            for (int c1 = 0; c1 < 16; c1++)
                t = fmaf(xin[c1], __ldg(&cw[c2 * 16 + c1]), t);
            t = fmaxf(t, 0.0f);
            s_xc[c2 * CS + po] = fmaf(__ldg(&g_sc[96 + c2]), t, __ldg(&g_sh[96 + c2]));
        }
    }
    __syncthreads();

    const int act  = s_active;
    const int lane = tid & 31;
    const int wg   = tid >> 5;
    const int prow = lane & 15;           // conflict-free lane map
    const int pcol = (lane >> 4) * 8;

    if (act) {
        // ---- d1: 1x1, 8 -> 16 ----  (8px x 2c2; pixel-pair accs)
        {
            const int c2base = wg * 2;
            const int po = prow * RS + pcol;
            ull acc[2][4];
#pragma unroll
            for (int c2 = 0; c2 < 2; c2++) {
                ull bv = dup2(__ldg(&d1b[c2base + c2]));
                acc[c2][0] = bv; acc[c2][1] = bv; acc[c2][2] = bv; acc[c2][3] = bv;
            }
#pragma unroll
            for (int c1 = 0; c1 < 8; c1++) {
                const float* p = s_xc + c1 * CS + po;
                float4 a = *(const float4*)p;
                float4 b = *(const float4*)(p + 4);
                ull va0 = pack2(a.x, a.y), va1 = pack2(a.z, a.w);
                ull vb0 = pack2(b.x, b.y), vb1 = pack2(b.z, b.w);
#pragma unroll
                for (int c2 = 0; c2 < 2; c2++) {
                    ull w = dup2(__ldg(&d1w[(c2base + c2) * 8 + c1]));
                    fma2(acc[c2][0], w, va0);
                    fma2(acc[c2][1], w, va1);
                    fma2(acc[c2][2], w, vb0);
                    fma2(acc[c2][3], w, vb1);
                }
            }
#pragma unroll
            for (int c2 = 0; c2 < 2; c2++) {
                int c = c2base + c2;
                float sc = __ldg(&g_sc[104 + c]), sh = __ldg(&g_sh[104 + c]);
                float2 f0 = unpack2(acc[c2][0]), f1 = unpack2(acc[c2][1]);
                float2 f2 = unpack2(acc[c2][2]), f3 = unpack2(acc[c2][3]);
                float4 o0, o1;
                o0.x = fmaf(sc, fmaxf(f0.x, 0.f), sh); o0.y = fmaf(sc, fmaxf(f0.y, 0.f), sh);
                o0.z = fmaf(sc, fmaxf(f1.x, 0.f), sh); o0.w = fmaf(sc, fmaxf(f1.y, 0.f), sh);
                o1.x = fmaf(sc, fmaxf(f2.x, 0.f), sh); o1.y = fmaf(sc, fmaxf(f2.y, 0.f), sh);
                o1.z = fmaf(sc, fmaxf(f3.x, 0.f), sh); o1.w = fmaf(sc, fmaxf(f3.y, 0.f), sh);
                *(float4*)(s_a + c * CS + po)     = o0;
                *(float4*)(s_a + c * CS + po + 4) = o1;
            }
        }
        __syncthreads();

        // ---- d2: 3x3, 16 -> 16 ----  (8px x 2c2; one c2-pair per warp)
        {
            const int pairb = wg;           // pair 0..7 -> c2 = 2*wg, 2*wg+1
            ull acc[8];
            {
                int c2 = 2 * pairb;
                ull bv = pack2(__ldg(&d2b[c2]), __ldg(&d2b[c2 + 1]));
#pragma unroll
                for (int k = 0; k < 8; k++) acc[k] = bv;
            }
            const float* sap = s_a + pcol;
            const ull* __restrict__ wbase = (const ull*)g_q2p + pairb;
#pragma unroll 4
            for (int c1 = 0; c1 < 16; c1++) {
                const float* cbase = sap + c1 * CS;
#pragma unroll
                for (int r = 0; r < 3; r++) {
                    int yy = prow - 1 + r;
                    float u0, u9; float4 m1, m2;
                    if ((unsigned)yy < 16u) {
                        const float* rp = cbase + yy * RS;
                        m1 = *(const float4*)rp;
                        m2 = *(const float4*)(rp + 4);
                        u0 = pcol ? rp[-1] : 0.f;
                        u9 = pcol ? 0.f : rp[8];
                    } else {
                        m1 = make_float4(0.f, 0.f, 0.f, 0.f);
                        m2 = m1; u0 = 0.f; u9 = 0.f;
                    }
                    ull vd[10] = {dup2(u0), dup2(m1.x), dup2(m1.y), dup2(m1.z), dup2(m1.w),
                                  dup2(m2.x), dup2(m2.y), dup2(m2.z), dup2(m2.w), dup2(u9)};
                    const ull* wrow = wbase + (c1 * 9 + r * 3) * 8;
#pragma unroll
                    for (int dx = 0; dx < 3; dx++) {
                        ull w = __ldg(wrow + dx * 8);
#pragma unroll
                        for (int k = 0; k < 8; k++) fma2(acc[k], w, vd[dx + k]);
                    }
                }
            }
            const int poc = prow * 16 + pcol;
            {
                int c2 = 2 * pairb;
                float sa = __ldg(&g_sc[120 + c2]), ha = __ldg(&g_sh[120 + c2]);
                float sb2 = __ldg(&g_sc[120 + c2 + 1]), hb = __ldg(&g_sh[120 + c2 + 1]);
                float4 oa0, oa1, ob0, ob1;
                float2 f;
                f = unpack2(acc[0]); oa0.x = fmaf(sa, fmaxf(f.x,0.f), ha); ob0.x = fmaf(sb2, fmaxf(f.y,0.f), hb);
                f = unpack2(acc[1]); oa0.y = fmaf(sa, fmaxf(f.x,0.f), ha); ob0.y = fmaf(sb2, fmaxf(f.y,0.f), hb);
                f = unpack2(acc[2]); oa0.z = fmaf(sa, fmaxf(f.x,0.f), ha); ob0.z = fmaf(sb2, fmaxf(f.y,0.f), hb);
                f = unpack2(acc[3]); oa0.w = fmaf(sa, fmaxf(f.x,0.f), ha); ob0.w = fmaf(sb2, fmaxf(f.y,0.f), hb);
                f = unpack2(acc[4]); oa1.x = fmaf(sa, fmaxf(f.x,0.f), ha); ob1.x = fmaf(sb2, fmaxf(f.y,0.f), hb);
                f = unpack2(acc[5]); oa1.y = fmaf(sa, fmaxf(f.x,0.f), ha); ob1.y = fmaf(sb2, fmaxf(f.y,0.f), hb);
                f = unpack2(acc[6]); oa1.z = fmaf(sa, fmaxf(f.x,0.f), ha); ob1.z = fmaf(sb2, fmaxf(f.y,0.f), hb);
                f = unpack2(acc[7]); oa1.w = fmaf(sa, fmaxf(f.x,0.f), ha); ob1.w = fmaf(sb2, fmaxf(f.y,0.f), hb);
                *(float4*)(s_b + c2 * 256 + poc)           = oa0;
                *(float4*)(s_b + c2 * 256 + poc + 4)       = oa1;
                *(float4*)(s_b + (c2 + 1) * 256 + poc)     = ob0;
                *(float4*)(s_b + (c2 + 1) * 256 + poc + 4) = ob1;
            }
        }
        __syncthreads();

        // ---- d3: 1x1, 16 -> 8 ----  (coalesced quad map; pixel-pair accs)
        {
            const int q      = tid & 63;
            const int c2base = (tid >> 6) * 2;
            ull acc[2][2];
#pragma unroll
            for (int c2 = 0; c2 < 2; c2++) {
                ull bv = dup2(__ldg(&d3b[c2base + c2]));
                acc[c2][0] = bv; acc[c2][1] = bv;
            }
#pragma unroll
            for (int c1 = 0; c1 < 16; c1++) {
                float4 v = *(const float4*)(s_b + c1 * 256 + q * 4);
                ull v0 = pack2(v.x, v.y), v1 = pack2(v.z, v.w);
#pragma unroll
                for (int c2 = 0; c2 < 2; c2++) {
                    ull w = dup2(__ldg(&d3w[(c2base + c2) * 16 + c1]));
                    fma2(acc[c2][0], w, v0);
                    fma2(acc[c2][1], w, v1);
                }
            }
#pragma unroll
            for (int c2 = 0; c2 < 2; c2++) {
                int c = c2base + c2;
                float sc = __ldg(&g_sc[136 + c]), sh = __ldg(&g_sh[136 + c]);
                float2 f0 = unpack2(acc[c2][0]), f1 = unpack2(acc[c2][1]);
                float4 o;
                o.x = fmaf(sc, fmaxf(f0.x, 0.f), sh);
                o.y = fmaf(sc, fmaxf(f0.y, 0.f), sh);
                o.z = fmaf(sc, fmaxf(f1.x, 0.f), sh);
                o.w = fmaf(sc, fmaxf(f1.y, 0.f), sh);
                *(float4*)(s_f + c * 256 + q * 4) = o;
            }
        }
        __syncthreads();
    }

    // fused maxpool -> g_x2p
    const float* srcp = act ? s_f : s_xc;
    const int chs = act ? 256 : CS;
    const int rs  = act ? 16 : RS;
#pragma unroll
    for (int k = 0; k < 2; k++) {
        int o = tid + k * 256;
        int c = o >> 6;
        int q = o & 63;
        int qy = q >> 3, qx = q & 7;
        const float* sp = &srcp[c * chs + (qy * 2) * rs + qx * 2];
        float mo = fmaxf(fmaxf(sp[0], sp[1]), fmaxf(sp[rs], sp[rs + 1]));
        g_x2p[((n * 8 + c) * 128 + by * 8 + qy) * 128 + (bx * 8 + qx)] = mo;
    }
}

// ---------------------------------------------------------------------------
// FC (split-K x32, vectorized) + softmax
// ---------------------------------------------------------------------------
__global__ void __launch_bounds__(256) fc_partial_kernel(const float* __restrict__ fc_w)
{
    const int b = blockIdx.x;       // 0..511
    const int n = b >> 5, s = b & 31;
    const int tid = threadIdx.x;
    const float4* f = (const float4*)(g_x2p + n * 131072 + s * 4096);
    const float4* w = (const float4*)(fc_w) + s * 1024;

    float part[10];
#pragma unroll
    for (int k = 0; k < 10; k++) part[k] = 0.0f;

#pragma unroll
    for (int j = tid; j < 1024; j += 256) {
        float4 fv = f[j];
#pragma unroll
        for (int k = 0; k < 10; k++) {
            float4 wv = __ldg(&w[k * 32768 + j]);
            part[k] += fv.x * wv.x + fv.y * wv.y + fv.z * wv.z + fv.w * wv.w;
        }
    }

    __shared__ float sred[10][256];
#pragma unroll
    for (int k = 0; k < 10; k++) sred[k][tid] = part[k];
    __syncthreads();
    for (int st = 128; st > 0; st >>= 1) {
        if (tid < st) {
#pragma unroll
            for (int k = 0; k < 10; k++) sred[k][tid] += sred[k][tid + st];
        }
        __syncthreads();
    }
    if (tid < 10) g_fcpart[(n * 32 + s) * 10 + tid] = sred[tid][0];
}

__global__ void fc_final_kernel(const float* __restrict__ fc_b, float* __restrict__ out)
{
    const int t = threadIdx.x;
    __shared__ float s_l[16][10];
    if (t < 160) {
        int n = t / 10, k = t - n * 10;
        float a = fc_b[k];
#pragma unroll
        for (int s = 0; s < 32; s++) a += g_fcpart[(n * 32 + s) * 10 + k];
        s_l[n][k] = a;
    }
    __syncthreads();
    if (t < 16) {
        float mx = -1e30f;
#pragma unroll
        for (int k = 0; k < 10; k++) mx = fmaxf(mx, s_l[t][k]);
        float e[10], se = 0.f;
#pragma unroll
        for (int k = 0; k < 10; k++) { e[k] = expf(s_l[t][k] - mx); se += e[k]; }
        float inv = 1.0f / se;
#pragma unroll
        for (int k = 0; k < 10; k++) out[t * 10 + k] = e[k] * inv;
    }
}

// ---------------------------------------------------------------------------
extern "C" void kernel_launch(void* const* d_in, const int* in_sizes, int n_in,
                              void* d_out, int out_size)
{
    const float* x      = (const float*)d_in[0];
    const float* mask   = (const float*)d_in[1];
    const float* s1_cw  = (const float*)d_in[2];
    const float* s1_cb  = (const float*)d_in[3];
    const float* s1_bn0 = (const float*)d_in[4];
    const float* s1_d1w = (const float*)d_in[5];
    const float* s1_d1b = (const float*)d_in[6];
    const float* s1_bn1 = (const float*)d_in[7];
    const float* s1_d2w = (const float*)d_in[8];
    const float* s1_d2b = (const float*)d_in[9];
    const float* s1_bn2 = (const float*)d_in[10];
    const float* s1_d3w = (const float*)d_in[11];
    const float* s1_d3b = (const float*)d_in[12];
    const float* s1_bn3 = (const float*)d_in[13];
    const float* s2_cw  = (const float*)d_in[14];
    const float* s2_cb  = (const float*)d_in[15];
    const float* s2_bn0 = (const float*)d_in[16];
    const float* s2_d1w = (const float*)d_in[17];
    const float* s2_d1b = (const float*)d_in[18];
    const float* s2_bn1 = (const float*)d_in[19];
    const float* s2_d2w = (const float*)d_in[20];
    const float* s2_d2b = (const float*)d_in[21];
    const float* s2_bn2 = (const float*)d_in[22];
    const float* s2_d3w = (const float*)d_in[23];
    const float* s2_d3b = (const float*)d_in[24];
    const float* s2_bn3 = (const float*)d_in[25];
    const float* fc_w   = (const float*)d_in[26];
    const float* fc_b   = (const float*)d_in[27];

    prep_kernel<<<1, 256>>>(s1_d2w, s2_d2w,
                            s1_bn0, s1_bn1, s1_bn2, s1_bn3,
                            s2_bn0, s2_bn1, s2_bn2, s2_bn3);

    stage1_all_kernel<<<16 * 32 * 32, 256>>>(x, mask, s1_cw, s1_cb);

    const int smem1 = 18432 * sizeof(float);   // 72 KB dynamic
    cudaFuncSetAttribute(stage1_active_kernel, cudaFuncAttributeMaxDynamicSharedMemorySize, smem1);
    stage1_active_kernel<<<16 * 32 * 32, 256, smem1>>>(
        x, s1_cw, s1_cb, s1_d1w, s1_d1b, s1_d2b, s1_d3w, s1_d3b);

    const int smem2 = 9216 * sizeof(float);    // 36 KB dynamic
    cudaFuncSetAttribute(stage2_kernel, cudaFuncAttributeMaxDynamicSharedMemorySize, smem2);
    stage2_kernel<<<16 * 16 * 16, 256, smem2>>>(
        s2_cw, s2_cb, s2_d1w, s2_d1b, s2_d2b, s2_d3w, s2_d3b);

    fc_partial_kernel<<<512, 256>>>(fc_w);
    fc_final_kernel<<<1, 256>>>(fc_b, (float*)d_out);
}